// round 13
// baseline (speedup 1.0000x reference)
#include <cuda_runtime.h>
#include <cuda_bf16.h>
#include <cstdint>

#define NB 4
#define NN 128
#define ND 256
#define NH_ 8

// ---------------- scratch (device globals; no allocation) ----------------
__device__ float g_cond[NB * 4 * ND];
__device__ float g_qkv[NB * NN * 3 * ND];
__device__ float g_logits[NB * NH_ * NN * NN];
__device__ float g_wv[NB * NN * ND];
__device__ __align__(16) __nv_bfloat16 g_nin_bf16[NB * NN * ND];
__device__ __align__(16) __nv_bfloat16 g_nout_bf16[NB * NN * ND];
__device__ __align__(16) __nv_bfloat16 g_h1_bf16[NB * NN * 4 * ND];
__device__ __align__(16) __nv_bfloat16 g_k_bf16[NB * NN * ND];
__device__ __align__(16) __nv_bfloat16 g_v_bf16[NB * NN * ND];
__device__ __align__(16) __nv_bfloat16 g_ea_bf16[NB * NN * NN * 128];  // LN(edges) bf16
__device__ __align__(16) __nv_bfloat16 g_wss_bf16[128 * 512];
__device__ __align__(16) __nv_bfloat16 g_weo_bf16[256 * 128];
__device__ __align__(16) __nv_bfloat16 g_wqkv_bf16[256 * 768];
__device__ __align__(16) __nv_bfloat16 g_we1_bf16[128 * 128];
__device__ __align__(16) __nv_bfloat16 g_we2_bf16[128 * 128];
__device__ __align__(16) __nv_bfloat16 g_wn1_bf16[256 * 1024];
__device__ __align__(16) __nv_bfloat16 g_wn2_bf16[1024 * 256];

__device__ __forceinline__ float warpSum(float v) {
#pragma unroll
    for (int o = 16; o; o >>= 1) v += __shfl_xor_sync(0xffffffffu, v, o);
    return v;
}
__device__ __forceinline__ float lrelu(float x) { return fmaxf(x, 0.1f * x); }

__device__ __forceinline__ uint32_t smem_to_u32(const void* p) {
    uint32_t a;
    asm("{ .reg .u64 tmp; cvta.to.shared.u64 tmp, %1; cvt.u32.u64 %0, tmp; }"
        : "=r"(a) : "l"(p));
    return a;
}

// ---------------- warp-level mma helpers ----------------
__device__ __forceinline__ void mma_bf16(float* c, const uint32_t* a, const uint32_t* b) {
    asm volatile(
        "mma.sync.aligned.m16n8k16.row.col.f32.bf16.bf16.f32 "
        "{%0,%1,%2,%3}, {%4,%5,%6,%7}, {%8,%9}, {%0,%1,%2,%3};"
        : "+f"(c[0]), "+f"(c[1]), "+f"(c[2]), "+f"(c[3])
        : "r"(a[0]), "r"(a[1]), "r"(a[2]), "r"(a[3]), "r"(b[0]), "r"(b[1]));
}
__device__ __forceinline__ void ldsm_x4(uint32_t* d, uint32_t addr) {
    asm volatile("ldmatrix.sync.aligned.m8n8.x4.shared.b16 {%0,%1,%2,%3}, [%4];"
                 : "=r"(d[0]), "=r"(d[1]), "=r"(d[2]), "=r"(d[3]) : "r"(addr));
}
__device__ __forceinline__ void ldsm_x4_t(uint32_t* d, uint32_t addr) {
    asm volatile("ldmatrix.sync.aligned.m8n8.x4.trans.shared.b16 {%0,%1,%2,%3}, [%4];"
                 : "=r"(d[0]), "=r"(d[1]), "=r"(d[2]), "=r"(d[3]) : "r"(addr));
}
__device__ __forceinline__ uint32_t ldsm_addr(uint32_t base, int stride_el, int row0, int col0, int lane) {
    return base + (uint32_t)(((row0 + (lane & 15)) * stride_el + col0 + ((lane >> 4) << 3)) * 2);
}

// ---------------- K0: convert weights to bf16 ----------------
__global__ void k_prep(const float* __restrict__ Wss, const float* __restrict__ Weo,
                       const float* __restrict__ Wqkv, const float* __restrict__ We1,
                       const float* __restrict__ We2, const float* __restrict__ Wn1,
                       const float* __restrict__ Wn2) {
    int i = blockIdx.x * 256 + threadIdx.x;
    if (i < 65536) g_wss_bf16[i] = __float2bfloat16(Wss[i]);
    if (i < 32768) g_weo_bf16[i] = __float2bfloat16(Weo[i]);
    if (i < 196608) g_wqkv_bf16[i] = __float2bfloat16(Wqkv[i]);
    if (i < 16384) {
        g_we1_bf16[i] = __float2bfloat16(We1[i]);
        g_we2_bf16[i] = __float2bfloat16(We2[i]);
    }
    if (i < 262144) {
        g_wn1_bf16[i] = __float2bfloat16(Wn1[i]);
        g_wn2_bf16[i] = __float2bfloat16(Wn2[i]);
    }
}

// ---------------- K0b: LN(edges) -> bf16 (off critical path) ----------------
__global__ void __launch_bounds__(512)
k_eln(const float* __restrict__ edges) {
    int q = blockIdx.x, b = blockIdx.y;
    int t = threadIdx.x, lane = t & 31, wid = t >> 5;
    for (int rr = 0; rr < 8; rr++) {
        int r = wid * 8 + rr;
        int gbase = ((b * 128 + q) * 128 + r) * 128;
        float v0 = edges[gbase + lane], v1 = edges[gbase + lane + 32],
              v2 = edges[gbase + lane + 64], v3 = edges[gbase + lane + 96];
        float s = warpSum(v0 + v1 + v2 + v3);
        float sq = warpSum(v0 * v0 + v1 * v1 + v2 * v2 + v3 * v3);
        float mean = s * (1.f / 128.f);
        float inv = rsqrtf(sq * (1.f / 128.f) - mean * mean + 1e-5f);
        float vv[4] = {v0, v1, v2, v3};
#pragma unroll
        for (int cc = 0; cc < 4; cc++) {
            int c = lane + cc * 32;
            g_ea_bf16[gbase + c] = __float2bfloat16(lrelu((vv[cc] - mean) * inv));
        }
    }
}

// ---------------- K1: cond = conds @ Wc + bc ----------------
__global__ void k_cond(const float* __restrict__ conds, const float* __restrict__ Wc,
                       const float* __restrict__ bc) {
    __shared__ float s_c[256];
    int b = blockIdx.x, t = threadIdx.x;
    if (t < 256) s_c[t] = conds[b * 256 + t];
    __syncthreads();
    float acc = bc[t];
#pragma unroll 4
    for (int c = 0; c < 256; c++) acc += s_c[c] * Wc[c * 1024 + t];
    g_cond[b * 1024 + t] = acc;
}

// ---------------- K2: n_in (bf16 out) ----------------
__global__ void k_nin(const float* __restrict__ nodes) {
    __shared__ float s_red[16];
    int row = blockIdx.x, t = threadIdx.x;
    int b = row >> 7;
    float x = nodes[row * 256 + t];
    float ws = warpSum(x);
    float wq = warpSum(x * x);
    int lane = t & 31, w = t >> 5;
    if (lane == 0) { s_red[w] = ws; s_red[8 + w] = wq; }
    __syncthreads();
    float s = 0.f, sq = 0.f;
#pragma unroll
    for (int i = 0; i < 8; i++) { s += s_red[i]; sq += s_red[8 + i]; }
    float mean = s * (1.f / 256.f);
    float var = sq * (1.f / 256.f) - mean * mean;
    float inv = rsqrtf(var + 1e-5f);
    float y = (x - mean) * inv;
    y = y * (1.f + g_cond[b * 1024 + t]) + g_cond[b * 1024 + 256 + t];
    g_nin_bf16[row * 256 + t] = __float2bfloat16(lrelu(y));
}

// ---------------- K3: qkv (mma bf16, 32-row tiles, warp=16x32, occ 2) ----------------
#define QA_OFF 0        // [32][264] bf16 = 16896
#define QB_OFF 33792    // [256][136] bf16 = 69632
#define QKV_SMEM 103424

__global__ void __launch_bounds__(256, 2)
k_qkv(const float* __restrict__ bqkv) {
    extern __shared__ char smem[];
    const uint32_t sb = smem_to_u32(smem);
    int t = threadIdx.x, lane = t & 31, wid = t >> 5;
    int mi = blockIdx.x, nj = blockIdx.y;
    int m0 = (wid & 1) * 16, n0 = (wid >> 1) * 32;
    int gid = lane >> 2, tig = lane & 3;

    for (int u = t; u < 1024; u += 256) {
        int r = u >> 5, c16 = u & 31;
        *(uint4*)(smem + QA_OFF + r * 528 + c16 * 16) =
            *(const uint4*)(g_nin_bf16 + (mi * 32 + r) * 256 + c16 * 8);
    }
    for (int u = t; u < 4096; u += 256) {
        int r = u >> 4, c16 = u & 15;
        *(uint4*)(smem + QB_OFF + r * 272 + c16 * 16) =
            *(const uint4*)(g_wqkv_bf16 + r * 768 + nj * 128 + c16 * 8);
    }
    __syncthreads();

    float c2[4][4];
#pragma unroll
    for (int i = 0; i < 4; i++)
#pragma unroll
        for (int e = 0; e < 4; e++) c2[i][e] = 0.f;
#pragma unroll
    for (int kk = 0; kk < 16; kk++) {
        uint32_t af[4];
        ldsm_x4(af, ldsm_addr(sb + QA_OFF, 264, m0, kk * 16, lane));
#pragma unroll
        for (int np = 0; np < 2; np++) {
            uint32_t bfr[4];
            ldsm_x4_t(bfr, ldsm_addr(sb + QB_OFF, 136, kk * 16, n0 + np * 16, lane));
            mma_bf16(c2[np * 2], af, bfr);
            mma_bf16(c2[np * 2 + 1], af, bfr + 2);
        }
    }
#pragma unroll
    for (int nt = 0; nt < 4; nt++) {
        int gcol = nj * 128 + n0 + nt * 8 + tig * 2;
        float b0 = __ldg(&bqkv[gcol]), b1 = __ldg(&bqkv[gcol + 1]);
        int rA = mi * 32 + m0 + gid, rB = rA + 8;
        float2 oA = { c2[nt][0] + b0, c2[nt][1] + b1 };
        float2 oB = { c2[nt][2] + b0, c2[nt][3] + b1 };
        *(float2*)&g_qkv[rA * 768 + gcol] = oA;
        *(float2*)&g_qkv[rB * 768 + gcol] = oB;
        if (nj >= 2 && nj < 4) {
            int kc = gcol - 256;
            *(__nv_bfloat162*)&g_k_bf16[rA * 256 + kc] = __floats2bfloat162_rn(oA.x, oA.y);
            *(__nv_bfloat162*)&g_k_bf16[rB * 256 + kc] = __floats2bfloat162_rn(oB.x, oB.y);
        } else if (nj >= 4) {
            int vc = gcol - 512;
            *(__nv_bfloat162*)&g_v_bf16[rA * 256 + vc] = __floats2bfloat162_rn(oA.x, oA.y);
            *(__nv_bfloat162*)&g_v_bf16[rB * 256 + vc] = __floats2bfloat162_rn(oB.x, oB.y);
        }
    }
}

// ---------------- K4: edge megakernel (512 threads / 16 warps) ----------------
#define E_A1   0
#define E_BS   34816
#define E_BC   53248
#define E_B2   0
#define E_NE   71680
#define E_K    139264
#define E_Q    206848
#define E_BSSB 207872
#define E_BEO  209920
#define E_SMEM 210432

__global__ void __launch_bounds__(512, 1)
k_edge_main(const float* __restrict__ edges,
            const float* __restrict__ bss,
            const float* __restrict__ beo,
            float* __restrict__ out_edges) {
    extern __shared__ char smem[];
    const uint32_t sb = smem_to_u32(smem);
    const int t = threadIdx.x, lane = t & 31, wid = t >> 5;
    const int q = blockIdx.x, b = blockIdx.y;
    const int strip = wid & 7, half = wid >> 3;
    const int m0 = strip * 16;
    const int gid = lane >> 2, tig = lane & 3;

    float* s_q = (float*)(smem + E_Q);
    float* s_bss = (float*)(smem + E_BSSB);
    float* s_beo = (float*)(smem + E_BEO);

    if (t < 256) s_q[t] = g_qkv[(b * 128 + q) * 768 + t];
    s_bss[t] = bss[t];
    if (t < 128) s_beo[t] = beo[t];

    for (int u = t; u < 4096; u += 512) {
        int r = u >> 5, c = u & 31;
        *(uint4*)(smem + E_K + r * 528 + c * 16) =
            *(const uint4*)(g_k_bf16 + (b * 128 + r) * 256 + c * 8);
    }
    for (int u = t; u < 1024; u += 512) {
        int r = u >> 3, c8 = u & 7;
        *(uint4*)(smem + E_BS + r * 144 + c8 * 16) =
            *(const uint4*)(g_wss_bf16 + r * 512 + c8 * 8);
        *(uint4*)(smem + E_BC + r * 144 + c8 * 16) =
            *(const uint4*)(g_wss_bf16 + r * 512 + 256 + c8 * 8);
    }
    // stage precomputed LN(edges) bf16 -> A1 [128][136]
    for (int u = t; u < 2048; u += 512) {
        int r = u >> 4, c16 = u & 15;
        *(uint4*)(smem + E_A1 + r * 272 + c16 * 16) =
            *(const uint4*)(g_ea_bf16 + ((b * 128 + q) * 128 + r) * 128 + c16 * 8);
    }
    __syncthreads();

    const float lscale = 0.17677669529663687f;
    const int jc = half * 32;

    for (int c = 0; c < 4; c++) {
        int j0 = c * 64;
        float cs[4][4], cf[4][4];
#pragma unroll
        for (int i = 0; i < 4; i++)
#pragma unroll
            for (int e = 0; e < 4; e++) { cs[i][e] = 0.f; cf[i][e] = 0.f; }
#pragma unroll
        for (int kk = 0; kk < 8; kk++) {
            uint32_t af[4];
            ldsm_x4(af, ldsm_addr(sb + E_A1, 136, m0, kk * 16, lane));
#pragma unroll
            for (int np = 0; np < 2; np++) {
                uint32_t bfr[4];
                ldsm_x4_t(bfr, ldsm_addr(sb + E_BS, 72, kk * 16, jc + np * 16, lane));
                mma_bf16(cs[np * 2], af, bfr);
                mma_bf16(cs[np * 2 + 1], af, bfr + 2);
                uint32_t cfr[4];
                ldsm_x4_t(cfr, ldsm_addr(sb + E_BC, 72, kk * 16, jc + np * 16, lane));
                mma_bf16(cf[np * 2], af, cfr);
                mma_bf16(cf[np * 2 + 1], af, cfr + 2);
            }
        }

        float hs0 = 0.f, hs1 = 0.f;
        int rA = m0 + gid;
#pragma unroll
        for (int nt = 0; nt < 4; nt++) {
            int colb = jc + nt * 8 + tig * 2;
            int j = j0 + colb;
            float q0 = s_q[j], q1 = s_q[j + 1];
            float bsh0 = s_bss[j], bsh1 = s_bss[j + 1];
            float bsc0 = s_bss[256 + j], bsc1 = s_bss[256 + j + 1];
            __nv_bfloat162 kp0 = *(const __nv_bfloat162*)(smem + E_K + rA * 528 + j * 2);
            float qp0 = q0 * __bfloat162float(kp0.x);
            float qp1 = q1 * __bfloat162float(kp0.y);
            float ne0 = fmaf(qp0, cf[nt][0] + bsc0, qp0) + (cs[nt][0] + bsh0);
            float ne1 = fmaf(qp1, cf[nt][1] + bsc1, qp1) + (cs[nt][1] + bsh1);
            __nv_bfloat162 kp1 = *(const __nv_bfloat162*)(smem + E_K + (rA + 8) * 528 + j * 2);
            float qp2 = q0 * __bfloat162float(kp1.x);
            float qp3 = q1 * __bfloat162float(kp1.y);
            float ne2 = fmaf(qp2, cf[nt][2] + bsc0, qp2) + (cs[nt][2] + bsh0);
            float ne3 = fmaf(qp3, cf[nt][3] + bsc1, qp3) + (cs[nt][3] + bsh1);
            hs0 += ne0 + ne1;
            hs1 += ne2 + ne3;
            *(__nv_bfloat162*)(smem + E_NE + rA * 528 + j * 2) =
                __floats2bfloat162_rn(lrelu(ne0), lrelu(ne1));
            *(__nv_bfloat162*)(smem + E_NE + (rA + 8) * 528 + j * 2) =
                __floats2bfloat162_rn(lrelu(ne2), lrelu(ne3));
        }
        hs0 += __shfl_xor_sync(0xffffffffu, hs0, 1); hs0 += __shfl_xor_sync(0xffffffffu, hs0, 2);
        hs1 += __shfl_xor_sync(0xffffffffu, hs1, 1); hs1 += __shfl_xor_sync(0xffffffffu, hs1, 2);
        if (tig == 0) {
            int h = c * 2 + half;
            g_logits[((b * 8 + h) * 128 + q) * 128 + rA] = hs0 * lscale;
            g_logits[((b * 8 + h) * 128 + q) * 128 + rA + 8] = hs1 * lscale;
        }
        __syncthreads();
        if (c < 3) {
            int j0n = (c + 1) * 64;
            for (int u = t; u < 1024; u += 512) {
                int r = u >> 3, c8 = u & 7;
                *(uint4*)(smem + E_BS + r * 144 + c8 * 16) =
                    *(const uint4*)(g_wss_bf16 + r * 512 + j0n + c8 * 8);
                *(uint4*)(smem + E_BC + r * 144 + c8 * 16) =
                    *(const uint4*)(g_wss_bf16 + r * 512 + 256 + j0n + c8 * 8);
            }
            __syncthreads();
        }
    }

    for (int u = t; u < 4096; u += 512) {
        int r = u >> 4, c16 = u & 15;
        *(uint4*)(smem + E_B2 + r * 272 + c16 * 16) =
            *(const uint4*)(g_weo_bf16 + r * 128 + c16 * 8);
    }
    __syncthreads();

    const int n0 = half * 64;
    float c2[8][4];
#pragma unroll
    for (int i = 0; i < 8; i++)
#pragma unroll
        for (int e = 0; e < 4; e++) c2[i][e] = 0.f;
#pragma unroll
    for (int kk = 0; kk < 16; kk++) {
        uint32_t af2[4];
        ldsm_x4(af2, ldsm_addr(sb + E_NE, 264, m0, kk * 16, lane));
#pragma unroll
        for (int np = 0; np < 4; np++) {
            uint32_t bfr[4];
            ldsm_x4_t(bfr, ldsm_addr(sb + E_B2, 136, kk * 16, n0 + np * 16, lane));
            mma_bf16(c2[np * 2], af2, bfr);
            mma_bf16(c2[np * 2 + 1], af2, bfr + 2);
        }
    }
#pragma unroll
    for (int nt = 0; nt < 8; nt++) {
        int n = n0 + nt * 8 + tig * 2;
        float be0 = s_beo[n], be1 = s_beo[n + 1];
        int rA = m0 + gid;
        int gbA = ((b * 128 + q) * 128 + rA) * 128 + n;
        float2 eA = *(const float2*)&edges[gbA];
        float2 oA = { eA.x + c2[nt][0] + be0, eA.y + c2[nt][1] + be1 };
        *(float2*)&out_edges[gbA] = oA;
        int gbB = gbA + 8 * 128;
        float2 eB = *(const float2*)&edges[gbB];
        float2 oB = { eB.x + c2[nt][2] + be0, eB.y + c2[nt][3] + be1 };
        *(float2*)&out_edges[gbB] = oB;
    }
}

// ---------------- K5: softmax (512 threads, 4/col) + wv = attn @ v ----------------
#define SW_L 0
#define SW_A 66048
#define SW_V 100864
#define SW_RED 111104
#define SW_SUM 113152
#define SW_SMEM 115200

__global__ void __launch_bounds__(512, 1) k_softmax_wv() {
    extern __shared__ char smem[];
    const uint32_t sb = smem_to_u32(smem);
    float* s_l = (float*)(smem + SW_L);
    float* s_red = (float*)(smem + SW_RED);
    float* s_sum = (float*)(smem + SW_SUM);
    int t = threadIdx.x, lane = t & 31, wid = t >> 5;
    int bh = blockIdx.x;
    int b = bh >> 3, h = bh & 7;
    const float* L = g_logits + bh * 128 * 128;

    for (int u = t; u < 16384; u += 512) {
        int qq = u >> 7, kk = u & 127;
        s_l[qq * 129 + kk] = L[u];
    }
    {
        int kk = t >> 2, c4 = t & 3;
        *(uint4*)(smem + SW_V + kk * 80 + c4 * 16) =
            *(const uint4*)(g_v_bf16 + (b * 128 + kk) * 256 + h * 32 + c4 * 8);
    }
    __syncthreads();

    {
        int k = t & 127, s = t >> 7;
        int q0 = s * 32;
        float m = -1e30f;
        for (int qq = q0; qq < q0 + 32; qq++) m = fmaxf(m, s_l[qq * 129 + k]);
        s_red[t] = m;
        __syncthreads();
        float gm = fmaxf(fmaxf(s_red[k], s_red[128 + k]),
                         fmaxf(s_red[256 + k], s_red[384 + k]));
        float sum = 0.f;
        for (int qq = q0; qq < q0 + 32; qq++) {
            float e = __expf(s_l[qq * 129 + k] - gm);
            s_l[qq * 129 + k] = e;
            sum += e;
        }
        s_sum[t] = sum;
        __syncthreads();
        float inv = 1.f / (s_sum[k] + s_sum[128 + k] + s_sum[256 + k] + s_sum[384 + k]);
        for (int qq = q0; qq < q0 + 32; qq++)
            *(__nv_bfloat16*)(smem + SW_A + (qq * 136 + k) * 2) =
                __float2bfloat16(s_l[qq * 129 + k] * inv);
    }
    __syncthreads();

    if (wid < 8) {
        int m0 = wid * 16;
        int gid = lane >> 2, tig = lane & 3;
        float acc[4][4];
#pragma unroll
        for (int i = 0; i < 4; i++)
#pragma unroll
            for (int e = 0; e < 4; e++) acc[i][e] = 0.f;
#pragma unroll
        for (int kk = 0; kk < 8; kk++) {
            uint32_t af[4];
            ldsm_x4(af, ldsm_addr(sb + SW_A, 136, m0, kk * 16, lane));
#pragma unroll
            for (int np = 0; np < 2; np++) {
                uint32_t bfr[4];
                ldsm_x4_t(bfr, ldsm_addr(sb + SW_V, 40, kk * 16, np * 16, lane));
                mma_bf16(acc[np * 2], af, bfr);
                mma_bf16(acc[np * 2 + 1], af, bfr + 2);
            }
        }
#pragma unroll
        for (int nt = 0; nt < 4; nt++) {
            int n = nt * 8 + tig * 2;
            int rA = m0 + gid;
            float2 oA = { acc[nt][0], acc[nt][1] };
            *(float2*)&g_wv[(b * 128 + rA) * 256 + h * 32 + n] = oA;
            float2 oB = { acc[nt][2], acc[nt][3] };
            *(float2*)&g_wv[(b * 128 + rA + 8) * 256 + h * 32 + n] = oB;
        }
    }
}

// ---------------- K6: fused node delta + residual + LN/FiLM -> n_out bf16 ----------------
__global__ void k_node_fuse(const float* __restrict__ nodes, const float* __restrict__ Wno,
                            const float* __restrict__ bno, float* __restrict__ out_nodes) {
    __shared__ float s_wv[256];
    __shared__ float s_red[16];
    int row = blockIdx.x, t = threadIdx.x;
    int b = row >> 7;
    s_wv[t] = g_wv[row * 256 + t];
    __syncthreads();
    float acc = bno[t];
#pragma unroll 4
    for (int c = 0; c < 256; c++) acc = fmaf(s_wv[c], Wno[c * 256 + t], acc);
    float x = nodes[row * 256 + t] + acc;
    out_nodes[row * 256 + t] = x;
    float ws = warpSum(x);
    float wq = warpSum(x * x);
    int lane = t & 31, w = t >> 5;
    if (lane == 0) { s_red[w] = ws; s_red[8 + w] = wq; }
    __syncthreads();
    float s = 0.f, sq = 0.f;
#pragma unroll
    for (int i = 0; i < 8; i++) { s += s_red[i]; sq += s_red[8 + i]; }
    float mean = s * (1.f / 256.f);
    float var = sq * (1.f / 256.f) - mean * mean;
    float inv = rsqrtf(var + 1e-5f);
    float y = (x - mean) * inv;
    y = y * (1.f + g_cond[b * 1024 + 512 + t]) + g_cond[b * 1024 + 768 + t];
    g_nout_bf16[row * 256 + t] = __float2bfloat16(lrelu(y));
}

// ---------------- K7b: h1 = lrelu(n_out @ Wn1 + bn1) ----------------
__global__ void __launch_bounds__(256, 2)
k_nmlp1(const float* __restrict__ bn1) {
    extern __shared__ char smem[];
    const uint32_t sb = smem_to_u32(smem);
    int t = threadIdx.x, lane = t & 31, wid = t >> 5;
    int mi = blockIdx.x, nj = blockIdx.y;
    int m0 = (wid & 1) * 16, n0 = (wid >> 1) * 32;
    int gid = lane >> 2, tig = lane & 3;

    for (int u = t; u < 1024; u += 256) {
        int r = u >> 5, c16 = u & 31;
        *(uint4*)(smem + QA_OFF + r * 528 + c16 * 16) =
            *(const uint4*)(g_nout_bf16 + (mi * 32 + r) * 256 + c16 * 8);
    }
    for (int u = t; u < 4096; u += 256) {
        int r = u >> 4, c16 = u & 15;
        *(uint4*)(smem + QB_OFF + r * 272 + c16 * 16) =
            *(const uint4*)(g_wn1_bf16 + r * 1024 + nj * 128 + c16 * 8);
    }
    __syncthreads();

    float c2[4][4];
#pragma unroll
    for (int i = 0; i < 4; i++)
#pragma unroll
        for (int e = 0; e < 4; e++) c2[i][e] = 0.f;
#pragma unroll
    for (int kk = 0; kk < 16; kk++) {
        uint32_t af[4];
        ldsm_x4(af, ldsm_addr(sb + QA_OFF, 264, m0, kk * 16, lane));
#pragma unroll
        for (int np = 0; np < 2; np++) {
            uint32_t bfr[4];
            ldsm_x4_t(bfr, ldsm_addr(sb + QB_OFF, 136, kk * 16, n0 + np * 16, lane));
            mma_bf16(c2[np * 2], af, bfr);
            mma_bf16(c2[np * 2 + 1], af, bfr + 2);
        }
    }
#pragma unroll
    for (int nt = 0; nt < 4; nt++) {
        int gcol = nj * 128 + n0 + nt * 8 + tig * 2;
        float b0 = __ldg(&bn1[gcol]), b1 = __ldg(&bn1[gcol + 1]);
        int rA = mi * 32 + m0 + gid, rB = rA + 8;
        *(__nv_bfloat162*)&g_h1_bf16[rA * 1024 + gcol] =
            __floats2bfloat162_rn(lrelu(c2[nt][0] + b0), lrelu(c2[nt][1] + b1));
        *(__nv_bfloat162*)&g_h1_bf16[rB * 1024 + gcol] =
            __floats2bfloat162_rn(lrelu(c2[nt][2] + b0), lrelu(c2[nt][3] + b1));
    }
}

// ---------------- K7c: nodes_out += h1 @ Wn2 + bn2 ----------------
__global__ void __launch_bounds__(256, 2)
k_nmlp2(const float* __restrict__ bn2, float* __restrict__ out_nodes) {
    extern __shared__ char smem[];
    const uint32_t sb = smem_to_u32(smem);
    int t = threadIdx.x, lane = t & 31, wid = t >> 5;
    int mi = blockIdx.x, nj = blockIdx.y;
    int m0 = (wid & 1) * 16, n0 = (wid >> 1) * 32;
    int gid = lane >> 2, tig = lane & 3;

    float c2[4][4];
#pragma unroll
    for (int i = 0; i < 4; i++)
#pragma unroll
        for (int e = 0; e < 4; e++) c2[i][e] = 0.f;

    for (int kc = 0; kc < 4; kc++) {
        for (int u = t; u < 1024; u += 256) {
            int r = u >> 5, c16 = u & 31;
            *(uint4*)(smem + QA_OFF + r * 528 + c16 * 16) =
                *(const uint4*)(g_h1_bf16 + (mi * 32 + r) * 1024 + kc * 256 + c16 * 8);
        }
        for (int u = t; u < 4096; u += 256) {
            int r = u >> 4, c16 = u & 15;
            *(uint4*)(smem + QB_OFF + r * 272 + c16 * 16) =
                *(const uint4*)(g_wn2_bf16 + (kc * 256 + r) * 256 + nj * 128 + c16 * 8);
        }
        __syncthreads();
#pragma unroll
        for (int kk = 0; kk < 16; kk++) {
            uint32_t af[4];
            ldsm_x4(af, ldsm_addr(sb + QA_OFF, 264, m0, kk * 16, lane));
#pragma unroll
            for (int np = 0; np < 2; np++) {
                uint32_t bfr[4];
                ldsm_x4_t(bfr, ldsm_addr(sb + QB_OFF, 136, kk * 16, n0 + np * 16, lane));
                mma_bf16(c2[np * 2], af, bfr);
                mma_bf16(c2[np * 2 + 1], af, bfr + 2);
            }
        }
        __syncthreads();
    }
#pragma unroll
    for (int nt = 0; nt < 4; nt++) {
        int gcol = nj * 128 + n0 + nt * 8 + tig * 2;
        float b0 = __ldg(&bn2[gcol]), b1 = __ldg(&bn2[gcol + 1]);
        int rA = mi * 32 + m0 + gid, rB = rA + 8;
        float2 xA = *(const float2*)&out_nodes[rA * 256 + gcol];
        float2 oA = { xA.x + c2[nt][0] + b0, xA.y + c2[nt][1] + b1 };
        *(float2*)&out_nodes[rA * 256 + gcol] = oA;
        float2 xB = *(const float2*)&out_nodes[rB * 256 + gcol];
        float2 oB = { xB.x + c2[nt][2] + b0, xB.y + c2[nt][3] + b1 };
        *(float2*)&out_nodes[rB * 256 + gcol] = oB;
    }
}

// ---------------- K8: edge LN-MLP (512 threads / 16 warps) ----------------
#define EM_W1 0
#define EM_W2 34816
#define EM_A  69632
#define EM_BE 104448
#define EM_SMEM 105472

__global__ void __launch_bounds__(512, 1)
k_edge_mlp(const float* __restrict__ be1, const float* __restrict__ be2,
           float* __restrict__ edges_io) {
    extern __shared__ char smem[];
    const uint32_t sb = smem_to_u32(smem);
    float* s_be1 = (float*)(smem + EM_BE);
    float* s_be2 = (float*)(smem + EM_BE + 512);
    int t = threadIdx.x, lane = t & 31, wid = t >> 5;
    int rows0 = blockIdx.x * 128;
    int strip = wid & 7, half = wid >> 3;
    int m0 = strip * 16, n0 = half * 64;
    int gid = lane >> 2, tig = lane & 3;

    for (int u = t; u < 2048; u += 512) {
        int r = u >> 4, c16 = u & 15;
        *(uint4*)(smem + EM_W1 + r * 272 + c16 * 16) = *(const uint4*)(g_we1_bf16 + r * 128 + c16 * 8);
        *(uint4*)(smem + EM_W2 + r * 272 + c16 * 16) = *(const uint4*)(g_we2_bf16 + r * 128 + c16 * 8);
    }
    if (t < 128) { s_be1[t] = be1[t]; s_be2[t] = be2[t]; }

    for (int rr = 0; rr < 8; rr++) {
        int r = wid * 8 + rr;
        int gbase = (rows0 + r) * 128;
        float v0 = edges_io[gbase + lane], v1 = edges_io[gbase + lane + 32],
              v2 = edges_io[gbase + lane + 64], v3 = edges_io[gbase + lane + 96];
        float s = warpSum(v0 + v1 + v2 + v3);
        float sq = warpSum(v0 * v0 + v1 * v1 + v2 * v2 + v3 * v3);
        float mean = s * (1.f / 128.f);
        float inv = rsqrtf(sq * (1.f / 128.f) - mean * mean + 1e-5f);
        float vv[4] = {v0, v1, v2, v3};
#pragma unroll
        for (int cc = 0; cc < 4; cc++) {
            int c = lane + cc * 32;
            *(__nv_bfloat16*)(smem + EM_A + r * 272 + c * 2) =
                __float2bfloat16(lrelu((vv[cc] - mean) * inv));
        }
    }
    __syncthreads();

    float c1[8][4];
#pragma unroll
    for (int i = 0; i < 8; i++)
#pragma unroll
        for (int e = 0; e < 4; e++) c1[i][e] = 0.f;
#pragma unroll
    for (int kk = 0; kk < 8; kk++) {
        uint32_t af[4];
        ldsm_x4(af, ldsm_addr(sb + EM_A, 136, m0, kk * 16, lane));
#pragma unroll
        for (int np = 0; np < 4; np++) {
            uint32_t bfr[4];
            ldsm_x4_t(bfr, ldsm_addr(sb + EM_W1, 136, kk * 16, n0 + np * 16, lane));
            mma_bf16(c1[np * 2], af, bfr);
            mma_bf16(c1[np * 2 + 1], af, bfr + 2);
        }
    }
    __syncthreads();
#pragma unroll
    for (int nt = 0; nt < 8; nt++) {
        int n = n0 + nt * 8 + tig * 2;
        float b0 = s_be1[n], b1 = s_be1[n + 1];
        int rA = m0 + gid;
        *(__nv_bfloat162*)(smem + EM_A + rA * 272 + n * 2) =
            __floats2bfloat162_rn(lrelu(c1[nt][0] + b0), lrelu(c1[nt][1] + b1));
        *(__nv_bfloat162*)(smem + EM_A + (rA + 8) * 272 + n * 2) =
            __floats2bfloat162_rn(lrelu(c1[nt][2] + b0), lrelu(c1[nt][3] + b1));
    }
    __syncthreads();

    float c2[8][4];
#pragma unroll
    for (int i = 0; i < 8; i++)
#pragma unroll
        for (int e = 0; e < 4; e++) c2[i][e] = 0.f;
#pragma unroll
    for (int kk = 0; kk < 8; kk++) {
        uint32_t af[4];
        ldsm_x4(af, ldsm_addr(sb + EM_A, 136, m0, kk * 16, lane));
#pragma unroll
        for (int np = 0; np < 4; np++) {
            uint32_t bfr[4];
            ldsm_x4_t(bfr, ldsm_addr(sb + EM_W2, 136, kk * 16, n0 + np * 16, lane));
            mma_bf16(c2[np * 2], af, bfr);
            mma_bf16(c2[np * 2 + 1], af, bfr + 2);
        }
    }
#pragma unroll
    for (int nt = 0; nt < 8; nt++) {
        int n = n0 + nt * 8 + tig * 2;
        float b0 = s_be2[n], b1 = s_be2[n + 1];
        int rA = m0 + gid;
        int gbA = (rows0 + rA) * 128 + n;
        float2 eA = *(const float2*)&edges_io[gbA];
        float2 oA = { eA.x + c2[nt][0] + b0, eA.y + c2[nt][1] + b1 };
        *(float2*)&edges_io[gbA] = oA;
        int gbB = gbA + 8 * 128;
        float2 eB = *(const float2*)&edges_io[gbB];
        float2 oB = { eB.x + c2[nt][2] + b0, eB.y + c2[nt][3] + b1 };
        *(float2*)&edges_io[gbB] = oB;
    }
}

// ---------------- stream/event infrastructure ----------------
struct ForkCtx {
    cudaStream_t s1 = nullptr;
    cudaEvent_t e_begin = nullptr, e_s1 = nullptr, e_main = nullptr, e_edge = nullptr;
    bool ok = false;
    ForkCtx() {
        ok = (cudaStreamCreateWithFlags(&s1, cudaStreamNonBlocking) == cudaSuccess) &&
             (cudaEventCreateWithFlags(&e_begin, cudaEventDisableTiming) == cudaSuccess) &&
             (cudaEventCreateWithFlags(&e_s1, cudaEventDisableTiming) == cudaSuccess) &&
             (cudaEventCreateWithFlags(&e_main, cudaEventDisableTiming) == cudaSuccess) &&
             (cudaEventCreateWithFlags(&e_edge, cudaEventDisableTiming) == cudaSuccess);
    }
};
static ForkCtx g_fork;

// ---------------- launch ----------------
extern "C" void kernel_launch(void* const* d_in, const int* in_sizes, int n_in,
                              void* d_out, int out_size) {
    const float* nodes = (const float*)d_in[0];
    const float* edges = (const float*)d_in[1];
    const float* conds = (const float*)d_in[2];
    const float* Wc   = (const float*)d_in[3];
    const float* bc   = (const float*)d_in[4];
    const float* Wqkv = (const float*)d_in[5];
    const float* bqkv = (const float*)d_in[6];
    const float* Wss  = (const float*)d_in[7];
    const float* bss  = (const float*)d_in[8];
    const float* Wno  = (const float*)d_in[9];
    const float* bno  = (const float*)d_in[10];
    const float* Weo  = (const float*)d_in[11];
    const float* beo  = (const float*)d_in[12];
    const float* Wn1  = (const float*)d_in[13];
    const float* bn1  = (const float*)d_in[14];
    const float* Wn2  = (const float*)d_in[15];
    const float* bn2  = (const float*)d_in[16];
    const float* We1  = (const float*)d_in[17];
    const float* be1  = (const float*)d_in[18];
    const float* We2  = (const float*)d_in[19];
    const float* be2  = (const float*)d_in[20];

    float* out_nodes = (float*)d_out;
    float* out_edges = out_nodes + NB * NN * ND;

    cudaFuncSetAttribute(k_qkv, cudaFuncAttributeMaxDynamicSharedMemorySize, QKV_SMEM);
    cudaFuncSetAttribute(k_edge_main, cudaFuncAttributeMaxDynamicSharedMemorySize, E_SMEM);
    cudaFuncSetAttribute(k_softmax_wv, cudaFuncAttributeMaxDynamicSharedMemorySize, SW_SMEM);
    cudaFuncSetAttribute(k_nmlp1, cudaFuncAttributeMaxDynamicSharedMemorySize, QKV_SMEM);
    cudaFuncSetAttribute(k_nmlp2, cudaFuncAttributeMaxDynamicSharedMemorySize, QKV_SMEM);
    cudaFuncSetAttribute(k_edge_mlp, cudaFuncAttributeMaxDynamicSharedMemorySize, EM_SMEM);

    if (g_fork.ok) {
        // fork 1: prep + eln on s1 || cond->nin->qkv on default
        cudaEventRecord(g_fork.e_begin, 0);
        cudaStreamWaitEvent(g_fork.s1, g_fork.e_begin, 0);
        k_prep<<<1024, 256, 0, g_fork.s1>>>(Wss, Weo, Wqkv, We1, We2, Wn1, Wn2);
        k_eln<<<dim3(128, 4), 512, 0, g_fork.s1>>>(edges);
        cudaEventRecord(g_fork.e_s1, g_fork.s1);
        k_cond<<<4, 1024>>>(conds, Wc, bc);
        k_nin<<<512, 256>>>(nodes);
        cudaStreamWaitEvent(0, g_fork.e_s1, 0);
        k_qkv<<<dim3(16, 6), 256, QKV_SMEM>>>(bqkv);
        k_edge_main<<<dim3(128, 4), 512, E_SMEM>>>(edges, bss, beo, out_edges);
        // fork 2: edge_mlp on s1 || node branch on default
        cudaEventRecord(g_fork.e_main, 0);
        cudaStreamWaitEvent(g_fork.s1, g_fork.e_main, 0);
        k_edge_mlp<<<512, 512, EM_SMEM, g_fork.s1>>>(be1, be2, out_edges);
        cudaEventRecord(g_fork.e_edge, g_fork.s1);
        k_softmax_wv<<<32, 512, SW_SMEM>>>();
        k_node_fuse<<<512, 256>>>(nodes, Wno, bno, out_nodes);
        k_nmlp1<<<dim3(16, 8), 256, QKV_SMEM>>>(bn1);
        k_nmlp2<<<dim3(16, 2), 256, QKV_SMEM>>>(bn2, out_nodes);
        cudaStreamWaitEvent(0, g_fork.e_edge, 0);
    } else {
        k_prep<<<1024, 256>>>(Wss, Weo, Wqkv, We1, We2, Wn1, Wn2);
        k_eln<<<dim3(128, 4), 512>>>(edges);
        k_cond<<<4, 1024>>>(conds, Wc, bc);
        k_nin<<<512, 256>>>(nodes);
        k_qkv<<<dim3(16, 6), 256, QKV_SMEM>>>(bqkv);
        k_edge_main<<<dim3(128, 4), 512, E_SMEM>>>(edges, bss, beo, out_edges);
        k_softmax_wv<<<32, 512, SW_SMEM>>>();
        k_node_fuse<<<512, 256>>>(nodes, Wno, bno, out_nodes);
        k_nmlp1<<<dim3(16, 8), 256, QKV_SMEM>>>(bn1);
        k_nmlp2<<<dim3(16, 2), 256, QKV_SMEM>>>(bn2, out_nodes);
        k_edge_mlp<<<512, 512, EM_SMEM>>>(be1, be2, out_edges);
    }
}

// round 14
// speedup vs baseline: 1.0094x; 1.0094x over previous
#include <cuda_runtime.h>
#include <cuda_bf16.h>
#include <cstdint>

#define NB 4
#define NN 128
#define ND 256
#define NH_ 8

// ---------------- scratch (device globals; no allocation) ----------------
__device__ float g_cond[NB * 4 * ND];
__device__ float g_qkv[NB * NN * 3 * ND];
__device__ float g_logits[NB * NH_ * NN * NN];
__device__ float g_wv[NB * NN * ND];
__device__ __align__(16) __nv_bfloat16 g_nin_bf16[NB * NN * ND];
__device__ __align__(16) __nv_bfloat16 g_nout_bf16[NB * NN * ND];
__device__ __align__(16) __nv_bfloat16 g_h1_bf16[NB * NN * 4 * ND];
__device__ __align__(16) __nv_bfloat16 g_k_bf16[NB * NN * ND];
__device__ __align__(16) __nv_bfloat16 g_v_bf16[NB * NN * ND];
__device__ __align__(16) __nv_bfloat16 g_ea_bf16[NB * NN * NN * 128];  // LN(edges) bf16
__device__ __align__(16) __nv_bfloat16 g_wss_bf16[128 * 512];
__device__ __align__(16) __nv_bfloat16 g_weo_bf16[256 * 128];
__device__ __align__(16) __nv_bfloat16 g_wqkv_bf16[256 * 768];
__device__ __align__(16) __nv_bfloat16 g_we1_bf16[128 * 128];
__device__ __align__(16) __nv_bfloat16 g_we2_bf16[128 * 128];
__device__ __align__(16) __nv_bfloat16 g_wn1_bf16[256 * 1024];
__device__ __align__(16) __nv_bfloat16 g_wn2_bf16[1024 * 256];

__device__ __forceinline__ float warpSum(float v) {
#pragma unroll
    for (int o = 16; o; o >>= 1) v += __shfl_xor_sync(0xffffffffu, v, o);
    return v;
}
__device__ __forceinline__ float lrelu(float x) { return fmaxf(x, 0.1f * x); }

__device__ __forceinline__ uint32_t smem_to_u32(const void* p) {
    uint32_t a;
    asm("{ .reg .u64 tmp; cvta.to.shared.u64 tmp, %1; cvt.u32.u64 %0, tmp; }"
        : "=r"(a) : "l"(p));
    return a;
}

// ---------------- warp-level mma helpers ----------------
__device__ __forceinline__ void mma_bf16(float* c, const uint32_t* a, const uint32_t* b) {
    asm volatile(
        "mma.sync.aligned.m16n8k16.row.col.f32.bf16.bf16.f32 "
        "{%0,%1,%2,%3}, {%4,%5,%6,%7}, {%8,%9}, {%0,%1,%2,%3};"
        : "+f"(c[0]), "+f"(c[1]), "+f"(c[2]), "+f"(c[3])
        : "r"(a[0]), "r"(a[1]), "r"(a[2]), "r"(a[3]), "r"(b[0]), "r"(b[1]));
}
__device__ __forceinline__ void ldsm_x4(uint32_t* d, uint32_t addr) {
    asm volatile("ldmatrix.sync.aligned.m8n8.x4.shared.b16 {%0,%1,%2,%3}, [%4];"
                 : "=r"(d[0]), "=r"(d[1]), "=r"(d[2]), "=r"(d[3]) : "r"(addr));
}
__device__ __forceinline__ void ldsm_x4_t(uint32_t* d, uint32_t addr) {
    asm volatile("ldmatrix.sync.aligned.m8n8.x4.trans.shared.b16 {%0,%1,%2,%3}, [%4];"
                 : "=r"(d[0]), "=r"(d[1]), "=r"(d[2]), "=r"(d[3]) : "r"(addr));
}
__device__ __forceinline__ uint32_t ldsm_addr(uint32_t base, int stride_el, int row0, int col0, int lane) {
    return base + (uint32_t)(((row0 + (lane & 15)) * stride_el + col0 + ((lane >> 4) << 3)) * 2);
}

// ---------------- K0: convert weights to bf16 ----------------
__global__ void k_prep(const float* __restrict__ Wss, const float* __restrict__ Weo,
                       const float* __restrict__ Wqkv, const float* __restrict__ We1,
                       const float* __restrict__ We2, const float* __restrict__ Wn1,
                       const float* __restrict__ Wn2) {
    int i = blockIdx.x * 256 + threadIdx.x;
    if (i < 65536) g_wss_bf16[i] = __float2bfloat16(Wss[i]);
    if (i < 32768) g_weo_bf16[i] = __float2bfloat16(Weo[i]);
    if (i < 196608) g_wqkv_bf16[i] = __float2bfloat16(Wqkv[i]);
    if (i < 16384) {
        g_we1_bf16[i] = __float2bfloat16(We1[i]);
        g_we2_bf16[i] = __float2bfloat16(We2[i]);
    }
    if (i < 262144) {
        g_wn1_bf16[i] = __float2bfloat16(Wn1[i]);
        g_wn2_bf16[i] = __float2bfloat16(Wn2[i]);
    }
}

// ---------------- K0b: LN(edges) -> bf16 (off critical path) ----------------
__global__ void __launch_bounds__(512)
k_eln(const float* __restrict__ edges) {
    int q = blockIdx.x, b = blockIdx.y;
    int t = threadIdx.x, lane = t & 31, wid = t >> 5;
    for (int rr = 0; rr < 8; rr++) {
        int r = wid * 8 + rr;
        int gbase = ((b * 128 + q) * 128 + r) * 128;
        float v0 = edges[gbase + lane], v1 = edges[gbase + lane + 32],
              v2 = edges[gbase + lane + 64], v3 = edges[gbase + lane + 96];
        float s = warpSum(v0 + v1 + v2 + v3);
        float sq = warpSum(v0 * v0 + v1 * v1 + v2 * v2 + v3 * v3);
        float mean = s * (1.f / 128.f);
        float inv = rsqrtf(sq * (1.f / 128.f) - mean * mean + 1e-5f);
        float vv[4] = {v0, v1, v2, v3};
#pragma unroll
        for (int cc = 0; cc < 4; cc++) {
            int c = lane + cc * 32;
            g_ea_bf16[gbase + c] = __float2bfloat16(lrelu((vv[cc] - mean) * inv));
        }
    }
}

// ---------------- K1: cond = conds @ Wc + bc ----------------
__global__ void k_cond(const float* __restrict__ conds, const float* __restrict__ Wc,
                       const float* __restrict__ bc) {
    __shared__ float s_c[256];
    int b = blockIdx.x, t = threadIdx.x;
    if (t < 256) s_c[t] = conds[b * 256 + t];
    __syncthreads();
    float acc = bc[t];
#pragma unroll 4
    for (int c = 0; c < 256; c++) acc += s_c[c] * Wc[c * 1024 + t];
    g_cond[b * 1024 + t] = acc;
}

// ---------------- K2: n_in (bf16 out) ----------------
__global__ void k_nin(const float* __restrict__ nodes) {
    __shared__ float s_red[16];
    int row = blockIdx.x, t = threadIdx.x;
    int b = row >> 7;
    float x = nodes[row * 256 + t];
    float ws = warpSum(x);
    float wq = warpSum(x * x);
    int lane = t & 31, w = t >> 5;
    if (lane == 0) { s_red[w] = ws; s_red[8 + w] = wq; }
    __syncthreads();
    float s = 0.f, sq = 0.f;
#pragma unroll
    for (int i = 0; i < 8; i++) { s += s_red[i]; sq += s_red[8 + i]; }
    float mean = s * (1.f / 256.f);
    float var = sq * (1.f / 256.f) - mean * mean;
    float inv = rsqrtf(var + 1e-5f);
    float y = (x - mean) * inv;
    y = y * (1.f + g_cond[b * 1024 + t]) + g_cond[b * 1024 + 256 + t];
    g_nin_bf16[row * 256 + t] = __float2bfloat16(lrelu(y));
}

// ---------------- K3: qkv (mma bf16, 32-row tiles, warp=16x32, occ 2) ----------------
#define QA_OFF 0        // [32][264] bf16 = 16896
#define QB_OFF 33792    // [256][136] bf16 = 69632
#define QKV_SMEM 103424

__global__ void __launch_bounds__(256, 2)
k_qkv(const float* __restrict__ bqkv) {
    extern __shared__ char smem[];
    const uint32_t sb = smem_to_u32(smem);
    int t = threadIdx.x, lane = t & 31, wid = t >> 5;
    int mi = blockIdx.x, nj = blockIdx.y;
    int m0 = (wid & 1) * 16, n0 = (wid >> 1) * 32;
    int gid = lane >> 2, tig = lane & 3;

    for (int u = t; u < 1024; u += 256) {
        int r = u >> 5, c16 = u & 31;
        *(uint4*)(smem + QA_OFF + r * 528 + c16 * 16) =
            *(const uint4*)(g_nin_bf16 + (mi * 32 + r) * 256 + c16 * 8);
    }
    for (int u = t; u < 4096; u += 256) {
        int r = u >> 4, c16 = u & 15;
        *(uint4*)(smem + QB_OFF + r * 272 + c16 * 16) =
            *(const uint4*)(g_wqkv_bf16 + r * 768 + nj * 128 + c16 * 8);
    }
    __syncthreads();

    float c2[4][4];
#pragma unroll
    for (int i = 0; i < 4; i++)
#pragma unroll
        for (int e = 0; e < 4; e++) c2[i][e] = 0.f;
#pragma unroll
    for (int kk = 0; kk < 16; kk++) {
        uint32_t af[4];
        ldsm_x4(af, ldsm_addr(sb + QA_OFF, 264, m0, kk * 16, lane));
#pragma unroll
        for (int np = 0; np < 2; np++) {
            uint32_t bfr[4];
            ldsm_x4_t(bfr, ldsm_addr(sb + QB_OFF, 136, kk * 16, n0 + np * 16, lane));
            mma_bf16(c2[np * 2], af, bfr);
            mma_bf16(c2[np * 2 + 1], af, bfr + 2);
        }
    }
#pragma unroll
    for (int nt = 0; nt < 4; nt++) {
        int gcol = nj * 128 + n0 + nt * 8 + tig * 2;
        float b0 = __ldg(&bqkv[gcol]), b1 = __ldg(&bqkv[gcol + 1]);
        int rA = mi * 32 + m0 + gid, rB = rA + 8;
        float2 oA = { c2[nt][0] + b0, c2[nt][1] + b1 };
        float2 oB = { c2[nt][2] + b0, c2[nt][3] + b1 };
        *(float2*)&g_qkv[rA * 768 + gcol] = oA;
        *(float2*)&g_qkv[rB * 768 + gcol] = oB;
        if (nj >= 2 && nj < 4) {
            int kc = gcol - 256;
            *(__nv_bfloat162*)&g_k_bf16[rA * 256 + kc] = __floats2bfloat162_rn(oA.x, oA.y);
            *(__nv_bfloat162*)&g_k_bf16[rB * 256 + kc] = __floats2bfloat162_rn(oB.x, oB.y);
        } else if (nj >= 4) {
            int vc = gcol - 512;
            *(__nv_bfloat162*)&g_v_bf16[rA * 256 + vc] = __floats2bfloat162_rn(oA.x, oA.y);
            *(__nv_bfloat162*)&g_v_bf16[rB * 256 + vc] = __floats2bfloat162_rn(oB.x, oB.y);
        }
    }
}

// ---------------- K4: edge megakernel (512 threads / 16 warps) ----------------
#define E_A1   0
#define E_BS   34816
#define E_BC   53248
#define E_B2   0
#define E_NE   71680
#define E_K    139264
#define E_Q    206848
#define E_BSSB 207872
#define E_BEO  209920
#define E_SMEM 210432

__global__ void __launch_bounds__(512, 1)
k_edge_main(const float* __restrict__ edges,
            const float* __restrict__ bss,
            const float* __restrict__ beo,
            float* __restrict__ out_edges) {
    extern __shared__ char smem[];
    const uint32_t sb = smem_to_u32(smem);
    const int t = threadIdx.x, lane = t & 31, wid = t >> 5;
    const int q = blockIdx.x, b = blockIdx.y;
    const int strip = wid & 7, half = wid >> 3;
    const int m0 = strip * 16;
    const int gid = lane >> 2, tig = lane & 3;

    float* s_q = (float*)(smem + E_Q);
    float* s_bss = (float*)(smem + E_BSSB);
    float* s_beo = (float*)(smem + E_BEO);

    if (t < 256) s_q[t] = g_qkv[(b * 128 + q) * 768 + t];
    s_bss[t] = bss[t];
    if (t < 128) s_beo[t] = beo[t];

    for (int u = t; u < 4096; u += 512) {
        int r = u >> 5, c = u & 31;
        *(uint4*)(smem + E_K + r * 528 + c * 16) =
            *(const uint4*)(g_k_bf16 + (b * 128 + r) * 256 + c * 8);
    }
    for (int u = t; u < 1024; u += 512) {
        int r = u >> 3, c8 = u & 7;
        *(uint4*)(smem + E_BS + r * 144 + c8 * 16) =
            *(const uint4*)(g_wss_bf16 + r * 512 + c8 * 8);
        *(uint4*)(smem + E_BC + r * 144 + c8 * 16) =
            *(const uint4*)(g_wss_bf16 + r * 512 + 256 + c8 * 8);
    }
    // stage precomputed LN(edges) bf16 -> A1 [128][136]
    for (int u = t; u < 2048; u += 512) {
        int r = u >> 4, c16 = u & 15;
        *(uint4*)(smem + E_A1 + r * 272 + c16 * 16) =
            *(const uint4*)(g_ea_bf16 + ((b * 128 + q) * 128 + r) * 128 + c16 * 8);
    }
    __syncthreads();

    const float lscale = 0.17677669529663687f;
    const int jc = half * 32;

    for (int c = 0; c < 4; c++) {
        int j0 = c * 64;
        float cs[4][4], cf[4][4];
#pragma unroll
        for (int i = 0; i < 4; i++)
#pragma unroll
            for (int e = 0; e < 4; e++) { cs[i][e] = 0.f; cf[i][e] = 0.f; }
#pragma unroll
        for (int kk = 0; kk < 8; kk++) {
            uint32_t af[4];
            ldsm_x4(af, ldsm_addr(sb + E_A1, 136, m0, kk * 16, lane));
#pragma unroll
            for (int np = 0; np < 2; np++) {
                uint32_t bfr[4];
                ldsm_x4_t(bfr, ldsm_addr(sb + E_BS, 72, kk * 16, jc + np * 16, lane));
                mma_bf16(cs[np * 2], af, bfr);
                mma_bf16(cs[np * 2 + 1], af, bfr + 2);
                uint32_t cfr[4];
                ldsm_x4_t(cfr, ldsm_addr(sb + E_BC, 72, kk * 16, jc + np * 16, lane));
                mma_bf16(cf[np * 2], af, cfr);
                mma_bf16(cf[np * 2 + 1], af, cfr + 2);
            }
        }

        float hs0 = 0.f, hs1 = 0.f;
        int rA = m0 + gid;
#pragma unroll
        for (int nt = 0; nt < 4; nt++) {
            int colb = jc + nt * 8 + tig * 2;
            int j = j0 + colb;
            float q0 = s_q[j], q1 = s_q[j + 1];
            float bsh0 = s_bss[j], bsh1 = s_bss[j + 1];
            float bsc0 = s_bss[256 + j], bsc1 = s_bss[256 + j + 1];
            __nv_bfloat162 kp0 = *(const __nv_bfloat162*)(smem + E_K + rA * 528 + j * 2);
            float qp0 = q0 * __bfloat162float(kp0.x);
            float qp1 = q1 * __bfloat162float(kp0.y);
            float ne0 = fmaf(qp0, cf[nt][0] + bsc0, qp0) + (cs[nt][0] + bsh0);
            float ne1 = fmaf(qp1, cf[nt][1] + bsc1, qp1) + (cs[nt][1] + bsh1);
            __nv_bfloat162 kp1 = *(const __nv_bfloat162*)(smem + E_K + (rA + 8) * 528 + j * 2);
            float qp2 = q0 * __bfloat162float(kp1.x);
            float qp3 = q1 * __bfloat162float(kp1.y);
            float ne2 = fmaf(qp2, cf[nt][2] + bsc0, qp2) + (cs[nt][2] + bsh0);
            float ne3 = fmaf(qp3, cf[nt][3] + bsc1, qp3) + (cs[nt][3] + bsh1);
            hs0 += ne0 + ne1;
            hs1 += ne2 + ne3;
            *(__nv_bfloat162*)(smem + E_NE + rA * 528 + j * 2) =
                __floats2bfloat162_rn(lrelu(ne0), lrelu(ne1));
            *(__nv_bfloat162*)(smem + E_NE + (rA + 8) * 528 + j * 2) =
                __floats2bfloat162_rn(lrelu(ne2), lrelu(ne3));
        }
        hs0 += __shfl_xor_sync(0xffffffffu, hs0, 1); hs0 += __shfl_xor_sync(0xffffffffu, hs0, 2);
        hs1 += __shfl_xor_sync(0xffffffffu, hs1, 1); hs1 += __shfl_xor_sync(0xffffffffu, hs1, 2);
        if (tig == 0) {
            int h = c * 2 + half;
            g_logits[((b * 8 + h) * 128 + q) * 128 + rA] = hs0 * lscale;
            g_logits[((b * 8 + h) * 128 + q) * 128 + rA + 8] = hs1 * lscale;
        }
        __syncthreads();
        if (c < 3) {
            int j0n = (c + 1) * 64;
            for (int u = t; u < 1024; u += 512) {
                int r = u >> 3, c8 = u & 7;
                *(uint4*)(smem + E_BS + r * 144 + c8 * 16) =
                    *(const uint4*)(g_wss_bf16 + r * 512 + j0n + c8 * 8);
                *(uint4*)(smem + E_BC + r * 144 + c8 * 16) =
                    *(const uint4*)(g_wss_bf16 + r * 512 + 256 + j0n + c8 * 8);
            }
            __syncthreads();
        }
    }

    for (int u = t; u < 4096; u += 512) {
        int r = u >> 4, c16 = u & 15;
        *(uint4*)(smem + E_B2 + r * 272 + c16 * 16) =
            *(const uint4*)(g_weo_bf16 + r * 128 + c16 * 8);
    }
    __syncthreads();

    const int n0 = half * 64;
    float c2[8][4];
#pragma unroll
    for (int i = 0; i < 8; i++)
#pragma unroll
        for (int e = 0; e < 4; e++) c2[i][e] = 0.f;
#pragma unroll
    for (int kk = 0; kk < 16; kk++) {
        uint32_t af2[4];
        ldsm_x4(af2, ldsm_addr(sb + E_NE, 264, m0, kk * 16, lane));
#pragma unroll
        for (int np = 0; np < 4; np++) {
            uint32_t bfr[4];
            ldsm_x4_t(bfr, ldsm_addr(sb + E_B2, 136, kk * 16, n0 + np * 16, lane));
            mma_bf16(c2[np * 2], af2, bfr);
            mma_bf16(c2[np * 2 + 1], af2, bfr + 2);
        }
    }
#pragma unroll
    for (int nt = 0; nt < 8; nt++) {
        int n = n0 + nt * 8 + tig * 2;
        float be0 = s_beo[n], be1 = s_beo[n + 1];
        int rA = m0 + gid;
        int gbA = ((b * 128 + q) * 128 + rA) * 128 + n;
        float2 eA = *(const float2*)&edges[gbA];
        float2 oA = { eA.x + c2[nt][0] + be0, eA.y + c2[nt][1] + be1 };
        *(float2*)&out_edges[gbA] = oA;
        int gbB = gbA + 8 * 128;
        float2 eB = *(const float2*)&edges[gbB];
        float2 oB = { eB.x + c2[nt][2] + be0, eB.y + c2[nt][3] + be1 };
        *(float2*)&out_edges[gbB] = oB;
    }
}

// ---------------- K5: softmax (512 threads, 4/col) + wv = attn @ v ----------------
#define SW_L 0
#define SW_A 66048
#define SW_V 100864
#define SW_RED 111104
#define SW_SUM 113152
#define SW_SMEM 115200

__global__ void __launch_bounds__(512, 1) k_softmax_wv() {
    extern __shared__ char smem[];
    const uint32_t sb = smem_to_u32(smem);
    float* s_l = (float*)(smem + SW_L);
    float* s_red = (float*)(smem + SW_RED);
    float* s_sum = (float*)(smem + SW_SUM);
    int t = threadIdx.x, lane = t & 31, wid = t >> 5;
    int bh = blockIdx.x;
    int b = bh >> 3, h = bh & 7;
    const float* L = g_logits + bh * 128 * 128;

    for (int u = t; u < 16384; u += 512) {
        int qq = u >> 7, kk = u & 127;
        s_l[qq * 129 + kk] = L[u];
    }
    {
        int kk = t >> 2, c4 = t & 3;
        *(uint4*)(smem + SW_V + kk * 80 + c4 * 16) =
            *(const uint4*)(g_v_bf16 + (b * 128 + kk) * 256 + h * 32 + c4 * 8);
    }
    __syncthreads();

    {
        int k = t & 127, s = t >> 7;
        int q0 = s * 32;
        float m = -1e30f;
        for (int qq = q0; qq < q0 + 32; qq++) m = fmaxf(m, s_l[qq * 129 + k]);
        s_red[t] = m;
        __syncthreads();
        float gm = fmaxf(fmaxf(s_red[k], s_red[128 + k]),
                         fmaxf(s_red[256 + k], s_red[384 + k]));
        float sum = 0.f;
        for (int qq = q0; qq < q0 + 32; qq++) {
            float e = __expf(s_l[qq * 129 + k] - gm);
            s_l[qq * 129 + k] = e;
            sum += e;
        }
        s_sum[t] = sum;
        __syncthreads();
        float inv = 1.f / (s_sum[k] + s_sum[128 + k] + s_sum[256 + k] + s_sum[384 + k]);
        for (int qq = q0; qq < q0 + 32; qq++)
            *(__nv_bfloat16*)(smem + SW_A + (qq * 136 + k) * 2) =
                __float2bfloat16(s_l[qq * 129 + k] * inv);
    }
    __syncthreads();

    if (wid < 8) {
        int m0 = wid * 16;
        int gid = lane >> 2, tig = lane & 3;
        float acc[4][4];
#pragma unroll
        for (int i = 0; i < 4; i++)
#pragma unroll
            for (int e = 0; e < 4; e++) acc[i][e] = 0.f;
#pragma unroll
        for (int kk = 0; kk < 8; kk++) {
            uint32_t af[4];
            ldsm_x4(af, ldsm_addr(sb + SW_A, 136, m0, kk * 16, lane));
#pragma unroll
            for (int np = 0; np < 2; np++) {
                uint32_t bfr[4];
                ldsm_x4_t(bfr, ldsm_addr(sb + SW_V, 40, kk * 16, np * 16, lane));
                mma_bf16(acc[np * 2], af, bfr);
                mma_bf16(acc[np * 2 + 1], af, bfr + 2);
            }
        }
#pragma unroll
        for (int nt = 0; nt < 4; nt++) {
            int n = nt * 8 + tig * 2;
            int rA = m0 + gid;
            float2 oA = { acc[nt][0], acc[nt][1] };
            *(float2*)&g_wv[(b * 128 + rA) * 256 + h * 32 + n] = oA;
            float2 oB = { acc[nt][2], acc[nt][3] };
            *(float2*)&g_wv[(b * 128 + rA + 8) * 256 + h * 32 + n] = oB;
        }
    }
}

// ---------------- K6: fused node delta + residual + LN/FiLM -> n_out bf16 ----------------
__global__ void k_node_fuse(const float* __restrict__ nodes, const float* __restrict__ Wno,
                            const float* __restrict__ bno, float* __restrict__ out_nodes) {
    __shared__ float s_wv[256];
    __shared__ float s_red[16];
    int row = blockIdx.x, t = threadIdx.x;
    int b = row >> 7;
    s_wv[t] = g_wv[row * 256 + t];
    __syncthreads();
    float acc = bno[t];
#pragma unroll 4
    for (int c = 0; c < 256; c++) acc = fmaf(s_wv[c], Wno[c * 256 + t], acc);
    float x = nodes[row * 256 + t] + acc;
    out_nodes[row * 256 + t] = x;
    float ws = warpSum(x);
    float wq = warpSum(x * x);
    int lane = t & 31, w = t >> 5;
    if (lane == 0) { s_red[w] = ws; s_red[8 + w] = wq; }
    __syncthreads();
    float s = 0.f, sq = 0.f;
#pragma unroll
    for (int i = 0; i < 8; i++) { s += s_red[i]; sq += s_red[8 + i]; }
    float mean = s * (1.f / 256.f);
    float var = sq * (1.f / 256.f) - mean * mean;
    float inv = rsqrtf(var + 1e-5f);
    float y = (x - mean) * inv;
    y = y * (1.f + g_cond[b * 1024 + 512 + t]) + g_cond[b * 1024 + 768 + t];
    g_nout_bf16[row * 256 + t] = __float2bfloat16(lrelu(y));
}

// ---------------- K7b: h1 = lrelu(n_out @ Wn1 + bn1) ----------------
__global__ void __launch_bounds__(256, 2)
k_nmlp1(const float* __restrict__ bn1) {
    extern __shared__ char smem[];
    const uint32_t sb = smem_to_u32(smem);
    int t = threadIdx.x, lane = t & 31, wid = t >> 5;
    int mi = blockIdx.x, nj = blockIdx.y;
    int m0 = (wid & 1) * 16, n0 = (wid >> 1) * 32;
    int gid = lane >> 2, tig = lane & 3;

    for (int u = t; u < 1024; u += 256) {
        int r = u >> 5, c16 = u & 31;
        *(uint4*)(smem + QA_OFF + r * 528 + c16 * 16) =
            *(const uint4*)(g_nout_bf16 + (mi * 32 + r) * 256 + c16 * 8);
    }
    for (int u = t; u < 4096; u += 256) {
        int r = u >> 4, c16 = u & 15;
        *(uint4*)(smem + QB_OFF + r * 272 + c16 * 16) =
            *(const uint4*)(g_wn1_bf16 + r * 1024 + nj * 128 + c16 * 8);
    }
    __syncthreads();

    float c2[4][4];
#pragma unroll
    for (int i = 0; i < 4; i++)
#pragma unroll
        for (int e = 0; e < 4; e++) c2[i][e] = 0.f;
#pragma unroll
    for (int kk = 0; kk < 16; kk++) {
        uint32_t af[4];
        ldsm_x4(af, ldsm_addr(sb + QA_OFF, 264, m0, kk * 16, lane));
#pragma unroll
        for (int np = 0; np < 2; np++) {
            uint32_t bfr[4];
            ldsm_x4_t(bfr, ldsm_addr(sb + QB_OFF, 136, kk * 16, n0 + np * 16, lane));
            mma_bf16(c2[np * 2], af, bfr);
            mma_bf16(c2[np * 2 + 1], af, bfr + 2);
        }
    }
#pragma unroll
    for (int nt = 0; nt < 4; nt++) {
        int gcol = nj * 128 + n0 + nt * 8 + tig * 2;
        float b0 = __ldg(&bn1[gcol]), b1 = __ldg(&bn1[gcol + 1]);
        int rA = mi * 32 + m0 + gid, rB = rA + 8;
        *(__nv_bfloat162*)&g_h1_bf16[rA * 1024 + gcol] =
            __floats2bfloat162_rn(lrelu(c2[nt][0] + b0), lrelu(c2[nt][1] + b1));
        *(__nv_bfloat162*)&g_h1_bf16[rB * 1024 + gcol] =
            __floats2bfloat162_rn(lrelu(c2[nt][2] + b0), lrelu(c2[nt][3] + b1));
    }
}

// ---------------- K7c: nodes_out += h1 @ Wn2 + bn2 ----------------
__global__ void __launch_bounds__(256, 2)
k_nmlp2(const float* __restrict__ bn2, float* __restrict__ out_nodes) {
    extern __shared__ char smem[];
    const uint32_t sb = smem_to_u32(smem);
    int t = threadIdx.x, lane = t & 31, wid = t >> 5;
    int mi = blockIdx.x, nj = blockIdx.y;
    int m0 = (wid & 1) * 16, n0 = (wid >> 1) * 32;
    int gid = lane >> 2, tig = lane & 3;

    float c2[4][4];
#pragma unroll
    for (int i = 0; i < 4; i++)
#pragma unroll
        for (int e = 0; e < 4; e++) c2[i][e] = 0.f;

    for (int kc = 0; kc < 4; kc++) {
        for (int u = t; u < 1024; u += 256) {
            int r = u >> 5, c16 = u & 31;
            *(uint4*)(smem + QA_OFF + r * 528 + c16 * 16) =
                *(const uint4*)(g_h1_bf16 + (mi * 32 + r) * 1024 + kc * 256 + c16 * 8);
        }
        for (int u = t; u < 4096; u += 256) {
            int r = u >> 4, c16 = u & 15;
            *(uint4*)(smem + QB_OFF + r * 272 + c16 * 16) =
                *(const uint4*)(g_wn2_bf16 + (kc * 256 + r) * 256 + nj * 128 + c16 * 8);
        }
        __syncthreads();
#pragma unroll
        for (int kk = 0; kk < 16; kk++) {
            uint32_t af[4];
            ldsm_x4(af, ldsm_addr(sb + QA_OFF, 264, m0, kk * 16, lane));
#pragma unroll
            for (int np = 0; np < 2; np++) {
                uint32_t bfr[4];
                ldsm_x4_t(bfr, ldsm_addr(sb + QB_OFF, 136, kk * 16, n0 + np * 16, lane));
                mma_bf16(c2[np * 2], af, bfr);
                mma_bf16(c2[np * 2 + 1], af, bfr + 2);
            }
        }
        __syncthreads();
    }
#pragma unroll
    for (int nt = 0; nt < 4; nt++) {
        int gcol = nj * 128 + n0 + nt * 8 + tig * 2;
        float b0 = __ldg(&bn2[gcol]), b1 = __ldg(&bn2[gcol + 1]);
        int rA = mi * 32 + m0 + gid, rB = rA + 8;
        float2 xA = *(const float2*)&out_nodes[rA * 256 + gcol];
        float2 oA = { xA.x + c2[nt][0] + b0, xA.y + c2[nt][1] + b1 };
        *(float2*)&out_nodes[rA * 256 + gcol] = oA;
        float2 xB = *(const float2*)&out_nodes[rB * 256 + gcol];
        float2 oB = { xB.x + c2[nt][2] + b0, xB.y + c2[nt][3] + b1 };
        *(float2*)&out_nodes[rB * 256 + gcol] = oB;
    }
}

// ---------------- K8: edge LN-MLP (512 threads / 16 warps) ----------------
#define EM_W1 0
#define EM_W2 34816
#define EM_A  69632
#define EM_BE 104448
#define EM_SMEM 105472

__global__ void __launch_bounds__(512, 1)
k_edge_mlp(const float* __restrict__ be1, const float* __restrict__ be2,
           float* __restrict__ edges_io) {
    extern __shared__ char smem[];
    const uint32_t sb = smem_to_u32(smem);
    float* s_be1 = (float*)(smem + EM_BE);
    float* s_be2 = (float*)(smem + EM_BE + 512);
    int t = threadIdx.x, lane = t & 31, wid = t >> 5;
    int rows0 = blockIdx.x * 128;
    int strip = wid & 7, half = wid >> 3;
    int m0 = strip * 16, n0 = half * 64;
    int gid = lane >> 2, tig = lane & 3;

    for (int u = t; u < 2048; u += 512) {
        int r = u >> 4, c16 = u & 15;
        *(uint4*)(smem + EM_W1 + r * 272 + c16 * 16) = *(const uint4*)(g_we1_bf16 + r * 128 + c16 * 8);
        *(uint4*)(smem + EM_W2 + r * 272 + c16 * 16) = *(const uint4*)(g_we2_bf16 + r * 128 + c16 * 8);
    }
    if (t < 128) { s_be1[t] = be1[t]; s_be2[t] = be2[t]; }

    for (int rr = 0; rr < 8; rr++) {
        int r = wid * 8 + rr;
        int gbase = (rows0 + r) * 128;
        float v0 = edges_io[gbase + lane], v1 = edges_io[gbase + lane + 32],
              v2 = edges_io[gbase + lane + 64], v3 = edges_io[gbase + lane + 96];
        float s = warpSum(v0 + v1 + v2 + v3);
        float sq = warpSum(v0 * v0 + v1 * v1 + v2 * v2 + v3 * v3);
        float mean = s * (1.f / 128.f);
        float inv = rsqrtf(sq * (1.f / 128.f) - mean * mean + 1e-5f);
        float vv[4] = {v0, v1, v2, v3};
#pragma unroll
        for (int cc = 0; cc < 4; cc++) {
            int c = lane + cc * 32;
            *(__nv_bfloat16*)(smem + EM_A + r * 272 + c * 2) =
                __float2bfloat16(lrelu((vv[cc] - mean) * inv));
        }
    }
    __syncthreads();

    float c1[8][4];
#pragma unroll
    for (int i = 0; i < 8; i++)
#pragma unroll
        for (int e = 0; e < 4; e++) c1[i][e] = 0.f;
#pragma unroll
    for (int kk = 0; kk < 8; kk++) {
        uint32_t af[4];
        ldsm_x4(af, ldsm_addr(sb + EM_A, 136, m0, kk * 16, lane));
#pragma unroll
        for (int np = 0; np < 4; np++) {
            uint32_t bfr[4];
            ldsm_x4_t(bfr, ldsm_addr(sb + EM_W1, 136, kk * 16, n0 + np * 16, lane));
            mma_bf16(c1[np * 2], af, bfr);
            mma_bf16(c1[np * 2 + 1], af, bfr + 2);
        }
    }
    __syncthreads();
#pragma unroll
    for (int nt = 0; nt < 8; nt++) {
        int n = n0 + nt * 8 + tig * 2;
        float b0 = s_be1[n], b1 = s_be1[n + 1];
        int rA = m0 + gid;
        *(__nv_bfloat162*)(smem + EM_A + rA * 272 + n * 2) =
            __floats2bfloat162_rn(lrelu(c1[nt][0] + b0), lrelu(c1[nt][1] + b1));
        *(__nv_bfloat162*)(smem + EM_A + (rA + 8) * 272 + n * 2) =
            __floats2bfloat162_rn(lrelu(c1[nt][2] + b0), lrelu(c1[nt][3] + b1));
    }
    __syncthreads();

    float c2[8][4];
#pragma unroll
    for (int i = 0; i < 8; i++)
#pragma unroll
        for (int e = 0; e < 4; e++) c2[i][e] = 0.f;
#pragma unroll
    for (int kk = 0; kk < 8; kk++) {
        uint32_t af[4];
        ldsm_x4(af, ldsm_addr(sb + EM_A, 136, m0, kk * 16, lane));
#pragma unroll
        for (int np = 0; np < 4; np++) {
            uint32_t bfr[4];
            ldsm_x4_t(bfr, ldsm_addr(sb + EM_W2, 136, kk * 16, n0 + np * 16, lane));
            mma_bf16(c2[np * 2], af, bfr);
            mma_bf16(c2[np * 2 + 1], af, bfr + 2);
        }
    }
#pragma unroll
    for (int nt = 0; nt < 8; nt++) {
        int n = n0 + nt * 8 + tig * 2;
        float b0 = s_be2[n], b1 = s_be2[n + 1];
        int rA = m0 + gid;
        int gbA = (rows0 + rA) * 128 + n;
        float2 eA = *(const float2*)&edges_io[gbA];
        float2 oA = { eA.x + c2[nt][0] + b0, eA.y + c2[nt][1] + b1 };
        *(float2*)&edges_io[gbA] = oA;
        int gbB = gbA + 8 * 128;
        float2 eB = *(const float2*)&edges_io[gbB];
        float2 oB = { eB.x + c2[nt][2] + b0, eB.y + c2[nt][3] + b1 };
        *(float2*)&edges_io[gbB] = oB;
    }
}

// ---------------- stream/event infrastructure ----------------
struct ForkCtx {
    cudaStream_t s1 = nullptr;
    cudaEvent_t e_begin = nullptr, e_prep = nullptr, e_eln = nullptr, e_main = nullptr, e_edge = nullptr;
    bool ok = false;
    ForkCtx() {
        ok = (cudaStreamCreateWithFlags(&s1, cudaStreamNonBlocking) == cudaSuccess) &&
             (cudaEventCreateWithFlags(&e_begin, cudaEventDisableTiming) == cudaSuccess) &&
             (cudaEventCreateWithFlags(&e_prep, cudaEventDisableTiming) == cudaSuccess) &&
             (cudaEventCreateWithFlags(&e_eln, cudaEventDisableTiming) == cudaSuccess) &&
             (cudaEventCreateWithFlags(&e_main, cudaEventDisableTiming) == cudaSuccess) &&
             (cudaEventCreateWithFlags(&e_edge, cudaEventDisableTiming) == cudaSuccess);
    }
};
static ForkCtx g_fork;

// ---------------- launch ----------------
extern "C" void kernel_launch(void* const* d_in, const int* in_sizes, int n_in,
                              void* d_out, int out_size) {
    const float* nodes = (const float*)d_in[0];
    const float* edges = (const float*)d_in[1];
    const float* conds = (const float*)d_in[2];
    const float* Wc   = (const float*)d_in[3];
    const float* bc   = (const float*)d_in[4];
    const float* Wqkv = (const float*)d_in[5];
    const float* bqkv = (const float*)d_in[6];
    const float* Wss  = (const float*)d_in[7];
    const float* bss  = (const float*)d_in[8];
    const float* Wno  = (const float*)d_in[9];
    const float* bno  = (const float*)d_in[10];
    const float* Weo  = (const float*)d_in[11];
    const float* beo  = (const float*)d_in[12];
    const float* Wn1  = (const float*)d_in[13];
    const float* bn1  = (const float*)d_in[14];
    const float* Wn2  = (const float*)d_in[15];
    const float* bn2  = (const float*)d_in[16];
    const float* We1  = (const float*)d_in[17];
    const float* be1  = (const float*)d_in[18];
    const float* We2  = (const float*)d_in[19];
    const float* be2  = (const float*)d_in[20];

    float* out_nodes = (float*)d_out;
    float* out_edges = out_nodes + NB * NN * ND;

    cudaFuncSetAttribute(k_qkv, cudaFuncAttributeMaxDynamicSharedMemorySize, QKV_SMEM);
    cudaFuncSetAttribute(k_edge_main, cudaFuncAttributeMaxDynamicSharedMemorySize, E_SMEM);
    cudaFuncSetAttribute(k_softmax_wv, cudaFuncAttributeMaxDynamicSharedMemorySize, SW_SMEM);
    cudaFuncSetAttribute(k_nmlp1, cudaFuncAttributeMaxDynamicSharedMemorySize, QKV_SMEM);
    cudaFuncSetAttribute(k_nmlp2, cudaFuncAttributeMaxDynamicSharedMemorySize, QKV_SMEM);
    cudaFuncSetAttribute(k_edge_mlp, cudaFuncAttributeMaxDynamicSharedMemorySize, EM_SMEM);

    if (g_fork.ok) {
        // fork 1: s1 runs prep (qkv dep) then eln (edge_main dep)
        cudaEventRecord(g_fork.e_begin, 0);
        cudaStreamWaitEvent(g_fork.s1, g_fork.e_begin, 0);
        k_prep<<<1024, 256, 0, g_fork.s1>>>(Wss, Weo, Wqkv, We1, We2, Wn1, Wn2);
        cudaEventRecord(g_fork.e_prep, g_fork.s1);
        k_eln<<<dim3(128, 4), 512, 0, g_fork.s1>>>(edges);
        cudaEventRecord(g_fork.e_eln, g_fork.s1);
        k_cond<<<4, 1024>>>(conds, Wc, bc);
        k_nin<<<512, 256>>>(nodes);
        cudaStreamWaitEvent(0, g_fork.e_prep, 0);   // qkv needs weights only
        k_qkv<<<dim3(16, 6), 256, QKV_SMEM>>>(bqkv);
        cudaStreamWaitEvent(0, g_fork.e_eln, 0);    // edge_main needs LN(edges)
        k_edge_main<<<dim3(128, 4), 512, E_SMEM>>>(edges, bss, beo, out_edges);
        // fork 2: edge_mlp on s1 || node branch on default
        cudaEventRecord(g_fork.e_main, 0);
        cudaStreamWaitEvent(g_fork.s1, g_fork.e_main, 0);
        k_edge_mlp<<<512, 512, EM_SMEM, g_fork.s1>>>(be1, be2, out_edges);
        cudaEventRecord(g_fork.e_edge, g_fork.s1);
        k_softmax_wv<<<32, 512, SW_SMEM>>>();
        k_node_fuse<<<512, 256>>>(nodes, Wno, bno, out_nodes);
        k_nmlp1<<<dim3(16, 8), 256, QKV_SMEM>>>(bn1);
        k_nmlp2<<<dim3(16, 2), 256, QKV_SMEM>>>(bn2, out_nodes);
        cudaStreamWaitEvent(0, g_fork.e_edge, 0);
    } else {
        k_prep<<<1024, 256>>>(Wss, Weo, Wqkv, We1, We2, Wn1, Wn2);
        k_eln<<<dim3(128, 4), 512>>>(edges);
        k_cond<<<4, 1024>>>(conds, Wc, bc);
        k_nin<<<512, 256>>>(nodes);
        k_qkv<<<dim3(16, 6), 256, QKV_SMEM>>>(bqkv);
        k_edge_main<<<dim3(128, 4), 512, E_SMEM>>>(edges, bss, beo, out_edges);
        k_softmax_wv<<<32, 512, SW_SMEM>>>();
        k_node_fuse<<<512, 256>>>(nodes, Wno, bno, out_nodes);
        k_nmlp1<<<dim3(16, 8), 256, QKV_SMEM>>>(bn1);
        k_nmlp2<<<dim3(16, 2), 256, QKV_SMEM>>>(bn2, out_nodes);
        k_edge_mlp<<<512, 512, EM_SMEM>>>(be1, be2, out_edges);
    }
}

// round 15
// speedup vs baseline: 1.0584x; 1.0485x over previous
#include <cuda_runtime.h>
#include <cuda_bf16.h>
#include <cstdint>

#define NB 4
#define NN 128
#define ND 256
#define NH_ 8

// ---------------- scratch (device globals; no allocation) ----------------
__device__ float g_cond[NB * 4 * ND];
__device__ float g_qkv[NB * NN * 3 * ND];
__device__ float g_logits[NB * NH_ * NN * NN];
__device__ float g_wv[NB * NN * ND];
__device__ __align__(16) __nv_bfloat16 g_nin_bf16[NB * NN * ND];
__device__ __align__(16) __nv_bfloat16 g_nout_bf16[NB * NN * ND];
__device__ __align__(16) __nv_bfloat16 g_h1_bf16[NB * NN * 4 * ND];
__device__ __align__(16) __nv_bfloat16 g_k_bf16[NB * NN * ND];
__device__ __align__(16) __nv_bfloat16 g_v_bf16[NB * NN * ND];
__device__ __align__(16) __nv_bfloat16 g_wss_bf16[128 * 512];
__device__ __align__(16) __nv_bfloat16 g_weo_bf16[256 * 128];
__device__ __align__(16) __nv_bfloat16 g_wqkv_bf16[256 * 768];
__device__ __align__(16) __nv_bfloat16 g_we1_bf16[128 * 128];
__device__ __align__(16) __nv_bfloat16 g_we2_bf16[128 * 128];
__device__ __align__(16) __nv_bfloat16 g_wn1_bf16[256 * 1024];
__device__ __align__(16) __nv_bfloat16 g_wn2_bf16[1024 * 256];

__device__ __forceinline__ float warpSum(float v) {
#pragma unroll
    for (int o = 16; o; o >>= 1) v += __shfl_xor_sync(0xffffffffu, v, o);
    return v;
}
__device__ __forceinline__ float lrelu(float x) { return fmaxf(x, 0.1f * x); }

__device__ __forceinline__ uint32_t smem_to_u32(const void* p) {
    uint32_t a;
    asm("{ .reg .u64 tmp; cvta.to.shared.u64 tmp, %1; cvt.u32.u64 %0, tmp; }"
        : "=r"(a) : "l"(p));
    return a;
}

// ---------------- warp-level mma helpers ----------------
__device__ __forceinline__ void mma_bf16(float* c, const uint32_t* a, const uint32_t* b) {
    asm volatile(
        "mma.sync.aligned.m16n8k16.row.col.f32.bf16.bf16.f32 "
        "{%0,%1,%2,%3}, {%4,%5,%6,%7}, {%8,%9}, {%0,%1,%2,%3};"
        : "+f"(c[0]), "+f"(c[1]), "+f"(c[2]), "+f"(c[3])
        : "r"(a[0]), "r"(a[1]), "r"(a[2]), "r"(a[3]), "r"(b[0]), "r"(b[1]));
}
__device__ __forceinline__ void ldsm_x4(uint32_t* d, uint32_t addr) {
    asm volatile("ldmatrix.sync.aligned.m8n8.x4.shared.b16 {%0,%1,%2,%3}, [%4];"
                 : "=r"(d[0]), "=r"(d[1]), "=r"(d[2]), "=r"(d[3]) : "r"(addr));
}
__device__ __forceinline__ void ldsm_x4_t(uint32_t* d, uint32_t addr) {
    asm volatile("ldmatrix.sync.aligned.m8n8.x4.trans.shared.b16 {%0,%1,%2,%3}, [%4];"
                 : "=r"(d[0]), "=r"(d[1]), "=r"(d[2]), "=r"(d[3]) : "r"(addr));
}
__device__ __forceinline__ uint32_t ldsm_addr(uint32_t base, int stride_el, int row0, int col0, int lane) {
    return base + (uint32_t)(((row0 + (lane & 15)) * stride_el + col0 + ((lane >> 4) << 3)) * 2);
}

// ---------------- K0: convert weights to bf16 ----------------
__global__ void k_prep(const float* __restrict__ Wss, const float* __restrict__ Weo,
                       const float* __restrict__ Wqkv, const float* __restrict__ We1,
                       const float* __restrict__ We2, const float* __restrict__ Wn1,
                       const float* __restrict__ Wn2) {
    int i = blockIdx.x * 256 + threadIdx.x;
    if (i < 65536) g_wss_bf16[i] = __float2bfloat16(Wss[i]);
    if (i < 32768) g_weo_bf16[i] = __float2bfloat16(Weo[i]);
    if (i < 196608) g_wqkv_bf16[i] = __float2bfloat16(Wqkv[i]);
    if (i < 16384) {
        g_we1_bf16[i] = __float2bfloat16(We1[i]);
        g_we2_bf16[i] = __float2bfloat16(We2[i]);
    }
    if (i < 262144) {
        g_wn1_bf16[i] = __float2bfloat16(Wn1[i]);
        g_wn2_bf16[i] = __float2bfloat16(Wn2[i]);
    }
}

// ---------------- K1: cond = conds @ Wc + bc ----------------
__global__ void k_cond(const float* __restrict__ conds, const float* __restrict__ Wc,
                       const float* __restrict__ bc) {
    __shared__ float s_c[256];
    int b = blockIdx.x, t = threadIdx.x;
    if (t < 256) s_c[t] = conds[b * 256 + t];
    __syncthreads();
    float acc = bc[t];
#pragma unroll 4
    for (int c = 0; c < 256; c++) acc += s_c[c] * Wc[c * 1024 + t];
    g_cond[b * 1024 + t] = acc;
}

// ---------------- K2: n_in (bf16 out) ----------------
__global__ void k_nin(const float* __restrict__ nodes) {
    __shared__ float s_red[16];
    int row = blockIdx.x, t = threadIdx.x;
    int b = row >> 7;
    float x = nodes[row * 256 + t];
    float ws = warpSum(x);
    float wq = warpSum(x * x);
    int lane = t & 31, w = t >> 5;
    if (lane == 0) { s_red[w] = ws; s_red[8 + w] = wq; }
    __syncthreads();
    float s = 0.f, sq = 0.f;
#pragma unroll
    for (int i = 0; i < 8; i++) { s += s_red[i]; sq += s_red[8 + i]; }
    float mean = s * (1.f / 256.f);
    float var = sq * (1.f / 256.f) - mean * mean;
    float inv = rsqrtf(var + 1e-5f);
    float y = (x - mean) * inv;
    y = y * (1.f + g_cond[b * 1024 + t]) + g_cond[b * 1024 + 256 + t];
    g_nin_bf16[row * 256 + t] = __float2bfloat16(lrelu(y));
}

// ---------------- K3: qkv (mma bf16, 32-row tiles, warp=16x32, occ 2) ----------------
#define QA_OFF 0        // [32][264] bf16 = 16896
#define QB_OFF 33792    // [256][136] bf16 = 69632
#define QKV_SMEM 103424

__global__ void __launch_bounds__(256, 2)
k_qkv(const float* __restrict__ bqkv) {
    extern __shared__ char smem[];
    const uint32_t sb = smem_to_u32(smem);
    int t = threadIdx.x, lane = t & 31, wid = t >> 5;
    int mi = blockIdx.x, nj = blockIdx.y;
    int m0 = (wid & 1) * 16, n0 = (wid >> 1) * 32;
    int gid = lane >> 2, tig = lane & 3;

    for (int u = t; u < 1024; u += 256) {
        int r = u >> 5, c16 = u & 31;
        *(uint4*)(smem + QA_OFF + r * 528 + c16 * 16) =
            *(const uint4*)(g_nin_bf16 + (mi * 32 + r) * 256 + c16 * 8);
    }
    for (int u = t; u < 4096; u += 256) {
        int r = u >> 4, c16 = u & 15;
        *(uint4*)(smem + QB_OFF + r * 272 + c16 * 16) =
            *(const uint4*)(g_wqkv_bf16 + r * 768 + nj * 128 + c16 * 8);
    }
    __syncthreads();

    float c2[4][4];
#pragma unroll
    for (int i = 0; i < 4; i++)
#pragma unroll
        for (int e = 0; e < 4; e++) c2[i][e] = 0.f;
#pragma unroll
    for (int kk = 0; kk < 16; kk++) {
        uint32_t af[4];
        ldsm_x4(af, ldsm_addr(sb + QA_OFF, 264, m0, kk * 16, lane));
#pragma unroll
        for (int np = 0; np < 2; np++) {
            uint32_t bfr[4];
            ldsm_x4_t(bfr, ldsm_addr(sb + QB_OFF, 136, kk * 16, n0 + np * 16, lane));
            mma_bf16(c2[np * 2], af, bfr);
            mma_bf16(c2[np * 2 + 1], af, bfr + 2);
        }
    }
#pragma unroll
    for (int nt = 0; nt < 4; nt++) {
        int gcol = nj * 128 + n0 + nt * 8 + tig * 2;
        float b0 = __ldg(&bqkv[gcol]), b1 = __ldg(&bqkv[gcol + 1]);
        int rA = mi * 32 + m0 + gid, rB = rA + 8;
        float2 oA = { c2[nt][0] + b0, c2[nt][1] + b1 };
        float2 oB = { c2[nt][2] + b0, c2[nt][3] + b1 };
        *(float2*)&g_qkv[rA * 768 + gcol] = oA;
        *(float2*)&g_qkv[rB * 768 + gcol] = oB;
        if (nj >= 2 && nj < 4) {
            int kc = gcol - 256;
            *(__nv_bfloat162*)&g_k_bf16[rA * 256 + kc] = __floats2bfloat162_rn(oA.x, oA.y);
            *(__nv_bfloat162*)&g_k_bf16[rB * 256 + kc] = __floats2bfloat162_rn(oB.x, oB.y);
        } else if (nj >= 4) {
            int vc = gcol - 512;
            *(__nv_bfloat162*)&g_v_bf16[rA * 256 + vc] = __floats2bfloat162_rn(oA.x, oA.y);
            *(__nv_bfloat162*)&g_v_bf16[rB * 256 + vc] = __floats2bfloat162_rn(oB.x, oB.y);
        }
    }
}

// ---------------- K4: edge megakernel (512 threads / 16 warps, K read from L2) ----------------
#define E_A1   0
#define E_BS   34816
#define E_BC   53248
#define E_B2   0
#define E_NE   71680
#define E_Q    139264
#define E_BSSB 140288
#define E_BEO  142336
#define E_SMEM 142848

__global__ void __launch_bounds__(512, 1)
k_edge_main(const float* __restrict__ edges,
            const float* __restrict__ bss,
            const float* __restrict__ beo,
            float* __restrict__ out_edges) {
    extern __shared__ char smem[];
    const uint32_t sb = smem_to_u32(smem);
    const int t = threadIdx.x, lane = t & 31, wid = t >> 5;
    const int q = blockIdx.x, b = blockIdx.y;
    const int strip = wid & 7, half = wid >> 3;
    const int m0 = strip * 16;
    const int gid = lane >> 2, tig = lane & 3;

    float* s_q = (float*)(smem + E_Q);
    float* s_bss = (float*)(smem + E_BSSB);
    float* s_beo = (float*)(smem + E_BEO);

    if (t < 256) s_q[t] = g_qkv[(b * 128 + q) * 768 + t];
    s_bss[t] = bss[t];
    if (t < 128) s_beo[t] = beo[t];

    for (int u = t; u < 1024; u += 512) {
        int r = u >> 3, c8 = u & 7;
        *(uint4*)(smem + E_BS + r * 144 + c8 * 16) =
            *(const uint4*)(g_wss_bf16 + r * 512 + c8 * 8);
        *(uint4*)(smem + E_BC + r * 144 + c8 * 16) =
            *(const uint4*)(g_wss_bf16 + r * 512 + 256 + c8 * 8);
    }
    for (int rr = 0; rr < 8; rr++) {
        int r = wid * 8 + rr;
        int gbase = ((b * 128 + q) * 128 + r) * 128;
        float v0 = edges[gbase + lane], v1 = edges[gbase + lane + 32],
              v2 = edges[gbase + lane + 64], v3 = edges[gbase + lane + 96];
        float s = warpSum(v0 + v1 + v2 + v3);
        float sq = warpSum(v0 * v0 + v1 * v1 + v2 * v2 + v3 * v3);
        float mean = s * (1.f / 128.f);
        float inv = rsqrtf(sq * (1.f / 128.f) - mean * mean + 1e-5f);
        float vv[4] = {v0, v1, v2, v3};
#pragma unroll
        for (int cc = 0; cc < 4; cc++) {
            int c = lane + cc * 32;
            *(__nv_bfloat16*)(smem + E_A1 + r * 272 + c * 2) =
                __float2bfloat16(lrelu((vv[cc] - mean) * inv));
        }
    }
    __syncthreads();

    const float lscale = 0.17677669529663687f;
    const int jc = half * 32;
    const __nv_bfloat16* kbase = g_k_bf16 + (b * 128) * 256;

    for (int c = 0; c < 4; c++) {
        int j0 = c * 64;
        float cs[4][4], cf[4][4];
#pragma unroll
        for (int i = 0; i < 4; i++)
#pragma unroll
            for (int e = 0; e < 4; e++) { cs[i][e] = 0.f; cf[i][e] = 0.f; }
#pragma unroll
        for (int kk = 0; kk < 8; kk++) {
            uint32_t af[4];
            ldsm_x4(af, ldsm_addr(sb + E_A1, 136, m0, kk * 16, lane));
#pragma unroll
            for (int np = 0; np < 2; np++) {
                uint32_t bfr[4];
                ldsm_x4_t(bfr, ldsm_addr(sb + E_BS, 72, kk * 16, jc + np * 16, lane));
                mma_bf16(cs[np * 2], af, bfr);
                mma_bf16(cs[np * 2 + 1], af, bfr + 2);
                uint32_t cfr[4];
                ldsm_x4_t(cfr, ldsm_addr(sb + E_BC, 72, kk * 16, jc + np * 16, lane));
                mma_bf16(cf[np * 2], af, cfr);
                mma_bf16(cf[np * 2 + 1], af, cfr + 2);
            }
        }

        float hs0 = 0.f, hs1 = 0.f;
        int rA = m0 + gid;
#pragma unroll
        for (int nt = 0; nt < 4; nt++) {
            int colb = jc + nt * 8 + tig * 2;
            int j = j0 + colb;
            float q0 = s_q[j], q1 = s_q[j + 1];
            float bsh0 = s_bss[j], bsh1 = s_bss[j + 1];
            float bsc0 = s_bss[256 + j], bsc1 = s_bss[256 + j + 1];
            __nv_bfloat162 kp0 = *(const __nv_bfloat162*)&kbase[rA * 256 + j];
            float qp0 = q0 * __bfloat162float(kp0.x);
            float qp1 = q1 * __bfloat162float(kp0.y);
            float ne0 = fmaf(qp0, cf[nt][0] + bsc0, qp0) + (cs[nt][0] + bsh0);
            float ne1 = fmaf(qp1, cf[nt][1] + bsc1, qp1) + (cs[nt][1] + bsh1);
            __nv_bfloat162 kp1 = *(const __nv_bfloat162*)&kbase[(rA + 8) * 256 + j];
            float qp2 = q0 * __bfloat162float(kp1.x);
            float qp3 = q1 * __bfloat162float(kp1.y);
            float ne2 = fmaf(qp2, cf[nt][2] + bsc0, qp2) + (cs[nt][2] + bsh0);
            float ne3 = fmaf(qp3, cf[nt][3] + bsc1, qp3) + (cs[nt][3] + bsh1);
            hs0 += ne0 + ne1;
            hs1 += ne2 + ne3;
            *(__nv_bfloat162*)(smem + E_NE + rA * 528 + j * 2) =
                __floats2bfloat162_rn(lrelu(ne0), lrelu(ne1));
            *(__nv_bfloat162*)(smem + E_NE + (rA + 8) * 528 + j * 2) =
                __floats2bfloat162_rn(lrelu(ne2), lrelu(ne3));
        }
        hs0 += __shfl_xor_sync(0xffffffffu, hs0, 1); hs0 += __shfl_xor_sync(0xffffffffu, hs0, 2);
        hs1 += __shfl_xor_sync(0xffffffffu, hs1, 1); hs1 += __shfl_xor_sync(0xffffffffu, hs1, 2);
        if (tig == 0) {
            int h = c * 2 + half;
            g_logits[((b * 8 + h) * 128 + q) * 128 + rA] = hs0 * lscale;
            g_logits[((b * 8 + h) * 128 + q) * 128 + rA + 8] = hs1 * lscale;
        }
        __syncthreads();
        if (c < 3) {
            int j0n = (c + 1) * 64;
            for (int u = t; u < 1024; u += 512) {
                int r = u >> 3, c8 = u & 7;
                *(uint4*)(smem + E_BS + r * 144 + c8 * 16) =
                    *(const uint4*)(g_wss_bf16 + r * 512 + j0n + c8 * 8);
                *(uint4*)(smem + E_BC + r * 144 + c8 * 16) =
                    *(const uint4*)(g_wss_bf16 + r * 512 + 256 + j0n + c8 * 8);
            }
            __syncthreads();
        }
    }

    for (int u = t; u < 4096; u += 512) {
        int r = u >> 4, c16 = u & 15;
        *(uint4*)(smem + E_B2 + r * 272 + c16 * 16) =
            *(const uint4*)(g_weo_bf16 + r * 128 + c16 * 8);
    }
    __syncthreads();

    const int n0 = half * 64;
    float c2[8][4];
#pragma unroll
    for (int i = 0; i < 8; i++)
#pragma unroll
        for (int e = 0; e < 4; e++) c2[i][e] = 0.f;
#pragma unroll
    for (int kk = 0; kk < 16; kk++) {
        uint32_t af2[4];
        ldsm_x4(af2, ldsm_addr(sb + E_NE, 264, m0, kk * 16, lane));
#pragma unroll
        for (int np = 0; np < 4; np++) {
            uint32_t bfr[4];
            ldsm_x4_t(bfr, ldsm_addr(sb + E_B2, 136, kk * 16, n0 + np * 16, lane));
            mma_bf16(c2[np * 2], af2, bfr);
            mma_bf16(c2[np * 2 + 1], af2, bfr + 2);
        }
    }
#pragma unroll
    for (int nt = 0; nt < 8; nt++) {
        int n = n0 + nt * 8 + tig * 2;
        float be0 = s_beo[n], be1 = s_beo[n + 1];
        int rA = m0 + gid;
        int gbA = ((b * 128 + q) * 128 + rA) * 128 + n;
        float2 eA = *(const float2*)&edges[gbA];
        float2 oA = { eA.x + c2[nt][0] + be0, eA.y + c2[nt][1] + be1 };
        *(float2*)&out_edges[gbA] = oA;
        int gbB = gbA + 8 * 128;
        float2 eB = *(const float2*)&edges[gbB];
        float2 oB = { eB.x + c2[nt][2] + be0, eB.y + c2[nt][3] + be1 };
        *(float2*)&out_edges[gbB] = oB;
    }
}

// ---------------- K5: softmax (512 threads, 4/col) + wv = attn @ v ----------------
#define SW_L 0
#define SW_A 66048
#define SW_V 100864
#define SW_RED 111104
#define SW_SUM 113152
#define SW_SMEM 115200

__global__ void __launch_bounds__(512, 1) k_softmax_wv() {
    extern __shared__ char smem[];
    const uint32_t sb = smem_to_u32(smem);
    float* s_l = (float*)(smem + SW_L);
    float* s_red = (float*)(smem + SW_RED);
    float* s_sum = (float*)(smem + SW_SUM);
    int t = threadIdx.x, lane = t & 31, wid = t >> 5;
    int bh = blockIdx.x;
    int b = bh >> 3, h = bh & 7;
    const float* L = g_logits + bh * 128 * 128;

    for (int u = t; u < 16384; u += 512) {
        int qq = u >> 7, kk = u & 127;
        s_l[qq * 129 + kk] = L[u];
    }
    {
        int kk = t >> 2, c4 = t & 3;
        *(uint4*)(smem + SW_V + kk * 80 + c4 * 16) =
            *(const uint4*)(g_v_bf16 + (b * 128 + kk) * 256 + h * 32 + c4 * 8);
    }
    __syncthreads();

    {
        int k = t & 127, s = t >> 7;
        int q0 = s * 32;
        float m = -1e30f;
        for (int qq = q0; qq < q0 + 32; qq++) m = fmaxf(m, s_l[qq * 129 + k]);
        s_red[t] = m;
        __syncthreads();
        float gm = fmaxf(fmaxf(s_red[k], s_red[128 + k]),
                         fmaxf(s_red[256 + k], s_red[384 + k]));
        float sum = 0.f;
        for (int qq = q0; qq < q0 + 32; qq++) {
            float e = __expf(s_l[qq * 129 + k] - gm);
            s_l[qq * 129 + k] = e;
            sum += e;
        }
        s_sum[t] = sum;
        __syncthreads();
        float inv = 1.f / (s_sum[k] + s_sum[128 + k] + s_sum[256 + k] + s_sum[384 + k]);
        for (int qq = q0; qq < q0 + 32; qq++)
            *(__nv_bfloat16*)(smem + SW_A + (qq * 136 + k) * 2) =
                __float2bfloat16(s_l[qq * 129 + k] * inv);
    }
    __syncthreads();

    if (wid < 8) {
        int m0 = wid * 16;
        int gid = lane >> 2, tig = lane & 3;
        float acc[4][4];
#pragma unroll
        for (int i = 0; i < 4; i++)
#pragma unroll
            for (int e = 0; e < 4; e++) acc[i][e] = 0.f;
#pragma unroll
        for (int kk = 0; kk < 8; kk++) {
            uint32_t af[4];
            ldsm_x4(af, ldsm_addr(sb + SW_A, 136, m0, kk * 16, lane));
#pragma unroll
            for (int np = 0; np < 2; np++) {
                uint32_t bfr[4];
                ldsm_x4_t(bfr, ldsm_addr(sb + SW_V, 40, kk * 16, np * 16, lane));
                mma_bf16(acc[np * 2], af, bfr);
                mma_bf16(acc[np * 2 + 1], af, bfr + 2);
            }
        }
#pragma unroll
        for (int nt = 0; nt < 4; nt++) {
            int n = nt * 8 + tig * 2;
            int rA = m0 + gid;
            float2 oA = { acc[nt][0], acc[nt][1] };
            *(float2*)&g_wv[(b * 128 + rA) * 256 + h * 32 + n] = oA;
            float2 oB = { acc[nt][2], acc[nt][3] };
            *(float2*)&g_wv[(b * 128 + rA + 8) * 256 + h * 32 + n] = oB;
        }
    }
}

// ---------------- K6: fused node delta + residual + LN/FiLM -> n_out bf16 ----------------
__global__ void k_node_fuse(const float* __restrict__ nodes, const float* __restrict__ Wno,
                            const float* __restrict__ bno, float* __restrict__ out_nodes) {
    __shared__ float s_wv[256];
    __shared__ float s_red[16];
    int row = blockIdx.x, t = threadIdx.x;
    int b = row >> 7;
    s_wv[t] = g_wv[row * 256 + t];
    __syncthreads();
    float acc = bno[t];
#pragma unroll 4
    for (int c = 0; c < 256; c++) acc = fmaf(s_wv[c], Wno[c * 256 + t], acc);
    float x = nodes[row * 256 + t] + acc;
    out_nodes[row * 256 + t] = x;
    float ws = warpSum(x);
    float wq = warpSum(x * x);
    int lane = t & 31, w = t >> 5;
    if (lane == 0) { s_red[w] = ws; s_red[8 + w] = wq; }
    __syncthreads();
    float s = 0.f, sq = 0.f;
#pragma unroll
    for (int i = 0; i < 8; i++) { s += s_red[i]; sq += s_red[8 + i]; }
    float mean = s * (1.f / 256.f);
    float var = sq * (1.f / 256.f) - mean * mean;
    float inv = rsqrtf(var + 1e-5f);
    float y = (x - mean) * inv;
    y = y * (1.f + g_cond[b * 1024 + 512 + t]) + g_cond[b * 1024 + 768 + t];
    g_nout_bf16[row * 256 + t] = __float2bfloat16(lrelu(y));
}

// ---------------- K7b: h1 = lrelu(n_out @ Wn1 + bn1) ----------------
__global__ void __launch_bounds__(256, 2)
k_nmlp1(const float* __restrict__ bn1) {
    extern __shared__ char smem[];
    const uint32_t sb = smem_to_u32(smem);
    int t = threadIdx.x, lane = t & 31, wid = t >> 5;
    int mi = blockIdx.x, nj = blockIdx.y;
    int m0 = (wid & 1) * 16, n0 = (wid >> 1) * 32;
    int gid = lane >> 2, tig = lane & 3;

    for (int u = t; u < 1024; u += 256) {
        int r = u >> 5, c16 = u & 31;
        *(uint4*)(smem + QA_OFF + r * 528 + c16 * 16) =
            *(const uint4*)(g_nout_bf16 + (mi * 32 + r) * 256 + c16 * 8);
    }
    for (int u = t; u < 4096; u += 256) {
        int r = u >> 4, c16 = u & 15;
        *(uint4*)(smem + QB_OFF + r * 272 + c16 * 16) =
            *(const uint4*)(g_wn1_bf16 + r * 1024 + nj * 128 + c16 * 8);
    }
    __syncthreads();

    float c2[4][4];
#pragma unroll
    for (int i = 0; i < 4; i++)
#pragma unroll
        for (int e = 0; e < 4; e++) c2[i][e] = 0.f;
#pragma unroll
    for (int kk = 0; kk < 16; kk++) {
        uint32_t af[4];
        ldsm_x4(af, ldsm_addr(sb + QA_OFF, 264, m0, kk * 16, lane));
#pragma unroll
        for (int np = 0; np < 2; np++) {
            uint32_t bfr[4];
            ldsm_x4_t(bfr, ldsm_addr(sb + QB_OFF, 136, kk * 16, n0 + np * 16, lane));
            mma_bf16(c2[np * 2], af, bfr);
            mma_bf16(c2[np * 2 + 1], af, bfr + 2);
        }
    }
#pragma unroll
    for (int nt = 0; nt < 4; nt++) {
        int gcol = nj * 128 + n0 + nt * 8 + tig * 2;
        float b0 = __ldg(&bn1[gcol]), b1 = __ldg(&bn1[gcol + 1]);
        int rA = mi * 32 + m0 + gid, rB = rA + 8;
        *(__nv_bfloat162*)&g_h1_bf16[rA * 1024 + gcol] =
            __floats2bfloat162_rn(lrelu(c2[nt][0] + b0), lrelu(c2[nt][1] + b1));
        *(__nv_bfloat162*)&g_h1_bf16[rB * 1024 + gcol] =
            __floats2bfloat162_rn(lrelu(c2[nt][2] + b0), lrelu(c2[nt][3] + b1));
    }
}

// ---------------- K7c: nodes_out += h1 @ Wn2 + bn2 ----------------
__global__ void __launch_bounds__(256, 2)
k_nmlp2(const float* __restrict__ bn2, float* __restrict__ out_nodes) {
    extern __shared__ char smem[];
    const uint32_t sb = smem_to_u32(smem);
    int t = threadIdx.x, lane = t & 31, wid = t >> 5;
    int mi = blockIdx.x, nj = blockIdx.y;
    int m0 = (wid & 1) * 16, n0 = (wid >> 1) * 32;
    int gid = lane >> 2, tig = lane & 3;

    float c2[4][4];
#pragma unroll
    for (int i = 0; i < 4; i++)
#pragma unroll
        for (int e = 0; e < 4; e++) c2[i][e] = 0.f;

    for (int kc = 0; kc < 4; kc++) {
        for (int u = t; u < 1024; u += 256) {
            int r = u >> 5, c16 = u & 31;
            *(uint4*)(smem + QA_OFF + r * 528 + c16 * 16) =
                *(const uint4*)(g_h1_bf16 + (mi * 32 + r) * 1024 + kc * 256 + c16 * 8);
        }
        for (int u = t; u < 4096; u += 256) {
            int r = u >> 4, c16 = u & 15;
            *(uint4*)(smem + QB_OFF + r * 272 + c16 * 16) =
                *(const uint4*)(g_wn2_bf16 + (kc * 256 + r) * 256 + nj * 128 + c16 * 8);
        }
        __syncthreads();
#pragma unroll
        for (int kk = 0; kk < 16; kk++) {
            uint32_t af[4];
            ldsm_x4(af, ldsm_addr(sb + QA_OFF, 264, m0, kk * 16, lane));
#pragma unroll
            for (int np = 0; np < 2; np++) {
                uint32_t bfr[4];
                ldsm_x4_t(bfr, ldsm_addr(sb + QB_OFF, 136, kk * 16, n0 + np * 16, lane));
                mma_bf16(c2[np * 2], af, bfr);
                mma_bf16(c2[np * 2 + 1], af, bfr + 2);
            }
        }
        __syncthreads();
    }
#pragma unroll
    for (int nt = 0; nt < 4; nt++) {
        int gcol = nj * 128 + n0 + nt * 8 + tig * 2;
        float b0 = __ldg(&bn2[gcol]), b1 = __ldg(&bn2[gcol + 1]);
        int rA = mi * 32 + m0 + gid, rB = rA + 8;
        float2 xA = *(const float2*)&out_nodes[rA * 256 + gcol];
        float2 oA = { xA.x + c2[nt][0] + b0, xA.y + c2[nt][1] + b1 };
        *(float2*)&out_nodes[rA * 256 + gcol] = oA;
        float2 xB = *(const float2*)&out_nodes[rB * 256 + gcol];
        float2 oB = { xB.x + c2[nt][2] + b0, xB.y + c2[nt][3] + b1 };
        *(float2*)&out_nodes[rB * 256 + gcol] = oB;
    }
}

// ---------------- K8: edge LN-MLP (512 threads / 16 warps) ----------------
#define EM_W1 0
#define EM_W2 34816
#define EM_A  69632
#define EM_BE 104448
#define EM_SMEM 105472

__global__ void __launch_bounds__(512, 1)
k_edge_mlp(const float* __restrict__ be1, const float* __restrict__ be2,
           float* __restrict__ edges_io) {
    extern __shared__ char smem[];
    const uint32_t sb = smem_to_u32(smem);
    float* s_be1 = (float*)(smem + EM_BE);
    float* s_be2 = (float*)(smem + EM_BE + 512);
    int t = threadIdx.x, lane = t & 31, wid = t >> 5;
    int rows0 = blockIdx.x * 128;
    int strip = wid & 7, half = wid >> 3;
    int m0 = strip * 16, n0 = half * 64;
    int gid = lane >> 2, tig = lane & 3;

    for (int u = t; u < 2048; u += 512) {
        int r = u >> 4, c16 = u & 15;
        *(uint4*)(smem + EM_W1 + r * 272 + c16 * 16) = *(const uint4*)(g_we1_bf16 + r * 128 + c16 * 8);
        *(uint4*)(smem + EM_W2 + r * 272 + c16 * 16) = *(const uint4*)(g_we2_bf16 + r * 128 + c16 * 8);
    }
    if (t < 128) { s_be1[t] = be1[t]; s_be2[t] = be2[t]; }

    for (int rr = 0; rr < 8; rr++) {
        int r = wid * 8 + rr;
        int gbase = (rows0 + r) * 128;
        float v0 = edges_io[gbase + lane], v1 = edges_io[gbase + lane + 32],
              v2 = edges_io[gbase + lane + 64], v3 = edges_io[gbase + lane + 96];
        float s = warpSum(v0 + v1 + v2 + v3);
        float sq = warpSum(v0 * v0 + v1 * v1 + v2 * v2 + v3 * v3);
        float mean = s * (1.f / 128.f);
        float inv = rsqrtf(sq * (1.f / 128.f) - mean * mean + 1e-5f);
        float vv[4] = {v0, v1, v2, v3};
#pragma unroll
        for (int cc = 0; cc < 4; cc++) {
            int c = lane + cc * 32;
            *(__nv_bfloat16*)(smem + EM_A + r * 272 + c * 2) =
                __float2bfloat16(lrelu((vv[cc] - mean) * inv));
        }
    }
    __syncthreads();

    float c1[8][4];
#pragma unroll
    for (int i = 0; i < 8; i++)
#pragma unroll
        for (int e = 0; e < 4; e++) c1[i][e] = 0.f;
#pragma unroll
    for (int kk = 0; kk < 8; kk++) {
        uint32_t af[4];
        ldsm_x4(af, ldsm_addr(sb + EM_A, 136, m0, kk * 16, lane));
#pragma unroll
        for (int np = 0; np < 4; np++) {
            uint32_t bfr[4];
            ldsm_x4_t(bfr, ldsm_addr(sb + EM_W1, 136, kk * 16, n0 + np * 16, lane));
            mma_bf16(c1[np * 2], af, bfr);
            mma_bf16(c1[np * 2 + 1], af, bfr + 2);
        }
    }
    __syncthreads();
#pragma unroll
    for (int nt = 0; nt < 8; nt++) {
        int n = n0 + nt * 8 + tig * 2;
        float b0 = s_be1[n], b1 = s_be1[n + 1];
        int rA = m0 + gid;
        *(__nv_bfloat162*)(smem + EM_A + rA * 272 + n * 2) =
            __floats2bfloat162_rn(lrelu(c1[nt][0] + b0), lrelu(c1[nt][1] + b1));
        *(__nv_bfloat162*)(smem + EM_A + (rA + 8) * 272 + n * 2) =
            __floats2bfloat162_rn(lrelu(c1[nt][2] + b0), lrelu(c1[nt][3] + b1));
    }
    __syncthreads();

    float c2[8][4];
#pragma unroll
    for (int i = 0; i < 8; i++)
#pragma unroll
        for (int e = 0; e < 4; e++) c2[i][e] = 0.f;
#pragma unroll
    for (int kk = 0; kk < 8; kk++) {
        uint32_t af[4];
        ldsm_x4(af, ldsm_addr(sb + EM_A, 136, m0, kk * 16, lane));
#pragma unroll
        for (int np = 0; np < 4; np++) {
            uint32_t bfr[4];
            ldsm_x4_t(bfr, ldsm_addr(sb + EM_W2, 136, kk * 16, n0 + np * 16, lane));
            mma_bf16(c2[np * 2], af, bfr);
            mma_bf16(c2[np * 2 + 1], af, bfr + 2);
        }
    }
#pragma unroll
    for (int nt = 0; nt < 8; nt++) {
        int n = n0 + nt * 8 + tig * 2;
        float b0 = s_be2[n], b1 = s_be2[n + 1];
        int rA = m0 + gid;
        int gbA = (rows0 + rA) * 128 + n;
        float2 eA = *(const float2*)&edges_io[gbA];
        float2 oA = { eA.x + c2[nt][0] + b0, eA.y + c2[nt][1] + b1 };
        *(float2*)&edges_io[gbA] = oA;
        int gbB = gbA + 8 * 128;
        float2 eB = *(const float2*)&edges_io[gbB];
        float2 oB = { eB.x + c2[nt][2] + b0, eB.y + c2[nt][3] + b1 };
        *(float2*)&edges_io[gbB] = oB;
    }
}

// ---------------- stream/event infrastructure ----------------
struct ForkCtx {
    cudaStream_t s1 = nullptr;
    cudaEvent_t e_begin = nullptr, e_prep = nullptr, e_main = nullptr, e_edge = nullptr;
    bool ok = false;
    ForkCtx() {
        ok = (cudaStreamCreateWithFlags(&s1, cudaStreamNonBlocking) == cudaSuccess) &&
             (cudaEventCreateWithFlags(&e_begin, cudaEventDisableTiming) == cudaSuccess) &&
             (cudaEventCreateWithFlags(&e_prep, cudaEventDisableTiming) == cudaSuccess) &&
             (cudaEventCreateWithFlags(&e_main, cudaEventDisableTiming) == cudaSuccess) &&
             (cudaEventCreateWithFlags(&e_edge, cudaEventDisableTiming) == cudaSuccess);
    }
};
static ForkCtx g_fork;

// ---------------- launch ----------------
extern "C" void kernel_launch(void* const* d_in, const int* in_sizes, int n_in,
                              void* d_out, int out_size) {
    const float* nodes = (const float*)d_in[0];
    const float* edges = (const float*)d_in[1];
    const float* conds = (const float*)d_in[2];
    const float* Wc   = (const float*)d_in[3];
    const float* bc   = (const float*)d_in[4];
    const float* Wqkv = (const float*)d_in[5];
    const float* bqkv = (const float*)d_in[6];
    const float* Wss  = (const float*)d_in[7];
    const float* bss  = (const float*)d_in[8];
    const float* Wno  = (const float*)d_in[9];
    const float* bno  = (const float*)d_in[10];
    const float* Weo  = (const float*)d_in[11];
    const float* beo  = (const float*)d_in[12];
    const float* Wn1  = (const float*)d_in[13];
    const float* bn1  = (const float*)d_in[14];
    const float* Wn2  = (const float*)d_in[15];
    const float* bn2  = (const float*)d_in[16];
    const float* We1  = (const float*)d_in[17];
    const float* be1  = (const float*)d_in[18];
    const float* We2  = (const float*)d_in[19];
    const float* be2  = (const float*)d_in[20];

    float* out_nodes = (float*)d_out;
    float* out_edges = out_nodes + NB * NN * ND;

    cudaFuncSetAttribute(k_qkv, cudaFuncAttributeMaxDynamicSharedMemorySize, QKV_SMEM);
    cudaFuncSetAttribute(k_edge_main, cudaFuncAttributeMaxDynamicSharedMemorySize, E_SMEM);
    cudaFuncSetAttribute(k_softmax_wv, cudaFuncAttributeMaxDynamicSharedMemorySize, SW_SMEM);
    cudaFuncSetAttribute(k_nmlp1, cudaFuncAttributeMaxDynamicSharedMemorySize, QKV_SMEM);
    cudaFuncSetAttribute(k_nmlp2, cudaFuncAttributeMaxDynamicSharedMemorySize, QKV_SMEM);
    cudaFuncSetAttribute(k_edge_mlp, cudaFuncAttributeMaxDynamicSharedMemorySize, EM_SMEM);

    if (g_fork.ok) {
        // fork 1: prep on s1 || cond->nin on default
        cudaEventRecord(g_fork.e_begin, 0);
        cudaStreamWaitEvent(g_fork.s1, g_fork.e_begin, 0);
        k_prep<<<1024, 256, 0, g_fork.s1>>>(Wss, Weo, Wqkv, We1, We2, Wn1, Wn2);
        cudaEventRecord(g_fork.e_prep, g_fork.s1);
        k_cond<<<4, 1024>>>(conds, Wc, bc);
        k_nin<<<512, 256>>>(nodes);
        cudaStreamWaitEvent(0, g_fork.e_prep, 0);
        k_qkv<<<dim3(16, 6), 256, QKV_SMEM>>>(bqkv);
        k_edge_main<<<dim3(128, 4), 512, E_SMEM>>>(edges, bss, beo, out_edges);
        // fork 2: edge_mlp on s1 || node branch on default
        cudaEventRecord(g_fork.e_main, 0);
        cudaStreamWaitEvent(g_fork.s1, g_fork.e_main, 0);
        k_edge_mlp<<<512, 512, EM_SMEM, g_fork.s1>>>(be1, be2, out_edges);
        cudaEventRecord(g_fork.e_edge, g_fork.s1);
        k_softmax_wv<<<32, 512, SW_SMEM>>>();
        k_node_fuse<<<512, 256>>>(nodes, Wno, bno, out_nodes);
        k_nmlp1<<<dim3(16, 8), 256, QKV_SMEM>>>(bn1);
        k_nmlp2<<<dim3(16, 2), 256, QKV_SMEM>>>(bn2, out_nodes);
        cudaStreamWaitEvent(0, g_fork.e_edge, 0);
    } else {
        k_prep<<<1024, 256>>>(Wss, Weo, Wqkv, We1, We2, Wn1, Wn2);
        k_cond<<<4, 1024>>>(conds, Wc, bc);
        k_nin<<<512, 256>>>(nodes);
        k_qkv<<<dim3(16, 6), 256, QKV_SMEM>>>(bqkv);
        k_edge_main<<<dim3(128, 4), 512, E_SMEM>>>(edges, bss, beo, out_edges);
        k_softmax_wv<<<32, 512, SW_SMEM>>>();
        k_node_fuse<<<512, 256>>>(nodes, Wno, bno, out_nodes);
        k_nmlp1<<<dim3(16, 8), 256, QKV_SMEM>>>(bn1);
        k_nmlp2<<<dim3(16, 2), 256, QKV_SMEM>>>(bn2, out_nodes);
        k_edge_mlp<<<512, 512, EM_SMEM>>>(be1, be2, out_edges);
    }
}

// round 16
// speedup vs baseline: 1.0925x; 1.0322x over previous
#include <cuda_runtime.h>
#include <cuda_bf16.h>
#include <cstdint>

#define NB 4
#define NN 128
#define ND 256
#define NH_ 8

// ---------------- scratch (device globals; no allocation) ----------------
__device__ float g_cond[NB * 4 * ND];
__device__ float g_qkv[NB * NN * 3 * ND];
__device__ float g_logits[NB * NH_ * NN * NN];
__device__ float g_wv[NB * NN * ND];
__device__ __align__(16) __nv_bfloat16 g_nin_bf16[NB * NN * ND];
__device__ __align__(16) __nv_bfloat16 g_nout_bf16[NB * NN * ND];
__device__ __align__(16) __nv_bfloat16 g_h1_bf16[NB * NN * 4 * ND];
__device__ __align__(16) __nv_bfloat16 g_k_bf16[NB * NN * ND];
__device__ __align__(16) __nv_bfloat16 g_v_bf16[NB * NN * ND];
__device__ __align__(16) __nv_bfloat16 g_wss_bf16[128 * 512];
__device__ __align__(16) __nv_bfloat16 g_weo_bf16[256 * 128];
__device__ __align__(16) __nv_bfloat16 g_wqkv_bf16[256 * 768];
__device__ __align__(16) __nv_bfloat16 g_we1_bf16[128 * 128];
__device__ __align__(16) __nv_bfloat16 g_we2_bf16[128 * 128];
__device__ __align__(16) __nv_bfloat16 g_wn1_bf16[256 * 1024];
__device__ __align__(16) __nv_bfloat16 g_wn2_bf16[1024 * 256];

__device__ __forceinline__ float warpSum(float v) {
#pragma unroll
    for (int o = 16; o; o >>= 1) v += __shfl_xor_sync(0xffffffffu, v, o);
    return v;
}
__device__ __forceinline__ float lrelu(float x) { return fmaxf(x, 0.1f * x); }

__device__ __forceinline__ uint32_t smem_to_u32(const void* p) {
    uint32_t a;
    asm("{ .reg .u64 tmp; cvta.to.shared.u64 tmp, %1; cvt.u32.u64 %0, tmp; }"
        : "=r"(a) : "l"(p));
    return a;
}

// ---------------- warp-level mma helpers ----------------
__device__ __forceinline__ void mma_bf16(float* c, const uint32_t* a, const uint32_t* b) {
    asm volatile(
        "mma.sync.aligned.m16n8k16.row.col.f32.bf16.bf16.f32 "
        "{%0,%1,%2,%3}, {%4,%5,%6,%7}, {%8,%9}, {%0,%1,%2,%3};"
        : "+f"(c[0]), "+f"(c[1]), "+f"(c[2]), "+f"(c[3])
        : "r"(a[0]), "r"(a[1]), "r"(a[2]), "r"(a[3]), "r"(b[0]), "r"(b[1]));
}
__device__ __forceinline__ void ldsm_x4(uint32_t* d, uint32_t addr) {
    asm volatile("ldmatrix.sync.aligned.m8n8.x4.shared.b16 {%0,%1,%2,%3}, [%4];"
                 : "=r"(d[0]), "=r"(d[1]), "=r"(d[2]), "=r"(d[3]) : "r"(addr));
}
__device__ __forceinline__ void ldsm_x4_t(uint32_t* d, uint32_t addr) {
    asm volatile("ldmatrix.sync.aligned.m8n8.x4.trans.shared.b16 {%0,%1,%2,%3}, [%4];"
                 : "=r"(d[0]), "=r"(d[1]), "=r"(d[2]), "=r"(d[3]) : "r"(addr));
}
__device__ __forceinline__ uint32_t ldsm_addr(uint32_t base, int stride_el, int row0, int col0, int lane) {
    return base + (uint32_t)(((row0 + (lane & 15)) * stride_el + col0 + ((lane >> 4) << 3)) * 2);
}

// ---------------- K0: convert weights to bf16 ----------------
__global__ void k_prep(const float* __restrict__ Wss, const float* __restrict__ Weo,
                       const float* __restrict__ Wqkv, const float* __restrict__ We1,
                       const float* __restrict__ We2, const float* __restrict__ Wn1,
                       const float* __restrict__ Wn2) {
    int i = blockIdx.x * 256 + threadIdx.x;
    if (i < 65536) g_wss_bf16[i] = __float2bfloat16(Wss[i]);
    if (i < 32768) g_weo_bf16[i] = __float2bfloat16(Weo[i]);
    if (i < 196608) g_wqkv_bf16[i] = __float2bfloat16(Wqkv[i]);
    if (i < 16384) {
        g_we1_bf16[i] = __float2bfloat16(We1[i]);
        g_we2_bf16[i] = __float2bfloat16(We2[i]);
    }
    if (i < 262144) {
        g_wn1_bf16[i] = __float2bfloat16(Wn1[i]);
        g_wn2_bf16[i] = __float2bfloat16(Wn2[i]);
    }
}

// ---------------- K1: cond = conds @ Wc + bc ----------------
__global__ void k_cond(const float* __restrict__ conds, const float* __restrict__ Wc,
                       const float* __restrict__ bc) {
    __shared__ float s_c[256];
    int b = blockIdx.x, t = threadIdx.x;
    if (t < 256) s_c[t] = conds[b * 256 + t];
    __syncthreads();
    float acc = bc[t];
#pragma unroll 4
    for (int c = 0; c < 256; c++) acc += s_c[c] * Wc[c * 1024 + t];
    g_cond[b * 1024 + t] = acc;
}

// ---------------- K2: n_in (bf16 out) ----------------
__global__ void k_nin(const float* __restrict__ nodes) {
    __shared__ float s_red[16];
    int row = blockIdx.x, t = threadIdx.x;
    int b = row >> 7;
    float x = nodes[row * 256 + t];
    float ws = warpSum(x);
    float wq = warpSum(x * x);
    int lane = t & 31, w = t >> 5;
    if (lane == 0) { s_red[w] = ws; s_red[8 + w] = wq; }
    __syncthreads();
    float s = 0.f, sq = 0.f;
#pragma unroll
    for (int i = 0; i < 8; i++) { s += s_red[i]; sq += s_red[8 + i]; }
    float mean = s * (1.f / 256.f);
    float var = sq * (1.f / 256.f) - mean * mean;
    float inv = rsqrtf(var + 1e-5f);
    float y = (x - mean) * inv;
    y = y * (1.f + g_cond[b * 1024 + t]) + g_cond[b * 1024 + 256 + t];
    g_nin_bf16[row * 256 + t] = __float2bfloat16(lrelu(y));
}

// ---------------- K3: qkv (mma bf16, 16-row tiles, warp=16x16, grid 32x6) ----------------
#define QA_OFF 0        // [16][264] bf16 = 8448
#define QB_OFF 8448     // [256][136] bf16 = 69632
#define QKV_SMEM 78080

__global__ void __launch_bounds__(256, 2)
k_qkv(const float* __restrict__ bqkv) {
    extern __shared__ char smem[];
    const uint32_t sb = smem_to_u32(smem);
    int t = threadIdx.x, lane = t & 31, wid = t >> 5;
    int mi = blockIdx.x, nj = blockIdx.y;
    int n0 = wid * 16;
    int gid = lane >> 2, tig = lane & 3;

    for (int u = t; u < 512; u += 256) {
        int r = u >> 5, c16 = u & 31;
        *(uint4*)(smem + QA_OFF + r * 528 + c16 * 16) =
            *(const uint4*)(g_nin_bf16 + (mi * 16 + r) * 256 + c16 * 8);
    }
    for (int u = t; u < 4096; u += 256) {
        int r = u >> 4, c16 = u & 15;
        *(uint4*)(smem + QB_OFF + r * 272 + c16 * 16) =
            *(const uint4*)(g_wqkv_bf16 + r * 768 + nj * 128 + c16 * 8);
    }
    __syncthreads();

    float c2[2][4];
#pragma unroll
    for (int i = 0; i < 2; i++)
#pragma unroll
        for (int e = 0; e < 4; e++) c2[i][e] = 0.f;
#pragma unroll
    for (int kk = 0; kk < 16; kk++) {
        uint32_t af[4];
        ldsm_x4(af, ldsm_addr(sb + QA_OFF, 264, 0, kk * 16, lane));
        uint32_t bfr[4];
        ldsm_x4_t(bfr, ldsm_addr(sb + QB_OFF, 136, kk * 16, n0, lane));
        mma_bf16(c2[0], af, bfr);
        mma_bf16(c2[1], af, bfr + 2);
    }
#pragma unroll
    for (int nt = 0; nt < 2; nt++) {
        int gcol = nj * 128 + n0 + nt * 8 + tig * 2;
        float b0 = __ldg(&bqkv[gcol]), b1 = __ldg(&bqkv[gcol + 1]);
        int rA = mi * 16 + gid, rB = rA + 8;
        float2 oA = { c2[nt][0] + b0, c2[nt][1] + b1 };
        float2 oB = { c2[nt][2] + b0, c2[nt][3] + b1 };
        *(float2*)&g_qkv[rA * 768 + gcol] = oA;
        *(float2*)&g_qkv[rB * 768 + gcol] = oB;
        if (nj >= 2 && nj < 4) {
            int kc = gcol - 256;
            *(__nv_bfloat162*)&g_k_bf16[rA * 256 + kc] = __floats2bfloat162_rn(oA.x, oA.y);
            *(__nv_bfloat162*)&g_k_bf16[rB * 256 + kc] = __floats2bfloat162_rn(oB.x, oB.y);
        } else if (nj >= 4) {
            int vc = gcol - 512;
            *(__nv_bfloat162*)&g_v_bf16[rA * 256 + vc] = __floats2bfloat162_rn(oA.x, oA.y);
            *(__nv_bfloat162*)&g_v_bf16[rB * 256 + vc] = __floats2bfloat162_rn(oB.x, oB.y);
        }
    }
}

// ---------------- K4: edge megakernel (512 threads / 16 warps, K staged in smem) ----------------
#define E_A1   0
#define E_BS   34816
#define E_BC   53248
#define E_B2   0
#define E_NE   71680
#define E_K    139264
#define E_Q    206848
#define E_BSSB 207872
#define E_BEO  209920
#define E_SMEM 210432

__global__ void __launch_bounds__(512, 1)
k_edge_main(const float* __restrict__ edges,
            const float* __restrict__ bss,
            const float* __restrict__ beo,
            float* __restrict__ out_edges) {
    extern __shared__ char smem[];
    const uint32_t sb = smem_to_u32(smem);
    const int t = threadIdx.x, lane = t & 31, wid = t >> 5;
    const int q = blockIdx.x, b = blockIdx.y;
    const int strip = wid & 7, half = wid >> 3;
    const int m0 = strip * 16;
    const int gid = lane >> 2, tig = lane & 3;

    float* s_q = (float*)(smem + E_Q);
    float* s_bss = (float*)(smem + E_BSSB);
    float* s_beo = (float*)(smem + E_BEO);

    if (t < 256) s_q[t] = g_qkv[(b * 128 + q) * 768 + t];
    s_bss[t] = bss[t];
    if (t < 128) s_beo[t] = beo[t];

    for (int u = t; u < 4096; u += 512) {
        int r = u >> 5, c = u & 31;
        *(uint4*)(smem + E_K + r * 528 + c * 16) =
            *(const uint4*)(g_k_bf16 + (b * 128 + r) * 256 + c * 8);
    }
    for (int u = t; u < 1024; u += 512) {
        int r = u >> 3, c8 = u & 7;
        *(uint4*)(smem + E_BS + r * 144 + c8 * 16) =
            *(const uint4*)(g_wss_bf16 + r * 512 + c8 * 8);
        *(uint4*)(smem + E_BC + r * 144 + c8 * 16) =
            *(const uint4*)(g_wss_bf16 + r * 512 + 256 + c8 * 8);
    }
    for (int rr = 0; rr < 8; rr++) {
        int r = wid * 8 + rr;
        int gbase = ((b * 128 + q) * 128 + r) * 128;
        float v0 = edges[gbase + lane], v1 = edges[gbase + lane + 32],
              v2 = edges[gbase + lane + 64], v3 = edges[gbase + lane + 96];
        float s = warpSum(v0 + v1 + v2 + v3);
        float sq = warpSum(v0 * v0 + v1 * v1 + v2 * v2 + v3 * v3);
        float mean = s * (1.f / 128.f);
        float inv = rsqrtf(sq * (1.f / 128.f) - mean * mean + 1e-5f);
        float vv[4] = {v0, v1, v2, v3};
#pragma unroll
        for (int cc = 0; cc < 4; cc++) {
            int c = lane + cc * 32;
            *(__nv_bfloat16*)(smem + E_A1 + r * 272 + c * 2) =
                __float2bfloat16(lrelu((vv[cc] - mean) * inv));
        }
    }
    __syncthreads();

    const float lscale = 0.17677669529663687f;
    const int jc = half * 32;

    for (int c = 0; c < 4; c++) {
        int j0 = c * 64;
        float cs[4][4], cf[4][4];
#pragma unroll
        for (int i = 0; i < 4; i++)
#pragma unroll
            for (int e = 0; e < 4; e++) { cs[i][e] = 0.f; cf[i][e] = 0.f; }
#pragma unroll
        for (int kk = 0; kk < 8; kk++) {
            uint32_t af[4];
            ldsm_x4(af, ldsm_addr(sb + E_A1, 136, m0, kk * 16, lane));
#pragma unroll
            for (int np = 0; np < 2; np++) {
                uint32_t bfr[4];
                ldsm_x4_t(bfr, ldsm_addr(sb + E_BS, 72, kk * 16, jc + np * 16, lane));
                mma_bf16(cs[np * 2], af, bfr);
                mma_bf16(cs[np * 2 + 1], af, bfr + 2);
                uint32_t cfr[4];
                ldsm_x4_t(cfr, ldsm_addr(sb + E_BC, 72, kk * 16, jc + np * 16, lane));
                mma_bf16(cf[np * 2], af, cfr);
                mma_bf16(cf[np * 2 + 1], af, cfr + 2);
            }
        }

        float hs0 = 0.f, hs1 = 0.f;
        int rA = m0 + gid;
#pragma unroll
        for (int nt = 0; nt < 4; nt++) {
            int colb = jc + nt * 8 + tig * 2;
            int j = j0 + colb;
            float q0 = s_q[j], q1 = s_q[j + 1];
            float bsh0 = s_bss[j], bsh1 = s_bss[j + 1];
            float bsc0 = s_bss[256 + j], bsc1 = s_bss[256 + j + 1];
            __nv_bfloat162 kp0 = *(const __nv_bfloat162*)(smem + E_K + rA * 528 + j * 2);
            float qp0 = q0 * __bfloat162float(kp0.x);
            float qp1 = q1 * __bfloat162float(kp0.y);
            float ne0 = fmaf(qp0, cf[nt][0] + bsc0, qp0) + (cs[nt][0] + bsh0);
            float ne1 = fmaf(qp1, cf[nt][1] + bsc1, qp1) + (cs[nt][1] + bsh1);
            __nv_bfloat162 kp1 = *(const __nv_bfloat162*)(smem + E_K + (rA + 8) * 528 + j * 2);
            float qp2 = q0 * __bfloat162float(kp1.x);
            float qp3 = q1 * __bfloat162float(kp1.y);
            float ne2 = fmaf(qp2, cf[nt][2] + bsc0, qp2) + (cs[nt][2] + bsh0);
            float ne3 = fmaf(qp3, cf[nt][3] + bsc1, qp3) + (cs[nt][3] + bsh1);
            hs0 += ne0 + ne1;
            hs1 += ne2 + ne3;
            *(__nv_bfloat162*)(smem + E_NE + rA * 528 + j * 2) =
                __floats2bfloat162_rn(lrelu(ne0), lrelu(ne1));
            *(__nv_bfloat162*)(smem + E_NE + (rA + 8) * 528 + j * 2) =
                __floats2bfloat162_rn(lrelu(ne2), lrelu(ne3));
        }
        hs0 += __shfl_xor_sync(0xffffffffu, hs0, 1); hs0 += __shfl_xor_sync(0xffffffffu, hs0, 2);
        hs1 += __shfl_xor_sync(0xffffffffu, hs1, 1); hs1 += __shfl_xor_sync(0xffffffffu, hs1, 2);
        if (tig == 0) {
            int h = c * 2 + half;
            g_logits[((b * 8 + h) * 128 + q) * 128 + rA] = hs0 * lscale;
            g_logits[((b * 8 + h) * 128 + q) * 128 + rA + 8] = hs1 * lscale;
        }
        __syncthreads();
        if (c < 3) {
            int j0n = (c + 1) * 64;
            for (int u = t; u < 1024; u += 512) {
                int r = u >> 3, c8 = u & 7;
                *(uint4*)(smem + E_BS + r * 144 + c8 * 16) =
                    *(const uint4*)(g_wss_bf16 + r * 512 + j0n + c8 * 8);
                *(uint4*)(smem + E_BC + r * 144 + c8 * 16) =
                    *(const uint4*)(g_wss_bf16 + r * 512 + 256 + j0n + c8 * 8);
            }
            __syncthreads();
        }
    }

    for (int u = t; u < 4096; u += 512) {
        int r = u >> 4, c16 = u & 15;
        *(uint4*)(smem + E_B2 + r * 272 + c16 * 16) =
            *(const uint4*)(g_weo_bf16 + r * 128 + c16 * 8);
    }
    __syncthreads();

    const int n0 = half * 64;
    float c2[8][4];
#pragma unroll
    for (int i = 0; i < 8; i++)
#pragma unroll
        for (int e = 0; e < 4; e++) c2[i][e] = 0.f;
#pragma unroll
    for (int kk = 0; kk < 16; kk++) {
        uint32_t af2[4];
        ldsm_x4(af2, ldsm_addr(sb + E_NE, 264, m0, kk * 16, lane));
#pragma unroll
        for (int np = 0; np < 4; np++) {
            uint32_t bfr[4];
            ldsm_x4_t(bfr, ldsm_addr(sb + E_B2, 136, kk * 16, n0 + np * 16, lane));
            mma_bf16(c2[np * 2], af2, bfr);
            mma_bf16(c2[np * 2 + 1], af2, bfr + 2);
        }
    }
#pragma unroll
    for (int nt = 0; nt < 8; nt++) {
        int n = n0 + nt * 8 + tig * 2;
        float be0 = s_beo[n], be1 = s_beo[n + 1];
        int rA = m0 + gid;
        int gbA = ((b * 128 + q) * 128 + rA) * 128 + n;
        float2 eA = *(const float2*)&edges[gbA];
        float2 oA = { eA.x + c2[nt][0] + be0, eA.y + c2[nt][1] + be1 };
        *(float2*)&out_edges[gbA] = oA;
        int gbB = gbA + 8 * 128;
        float2 eB = *(const float2*)&edges[gbB];
        float2 oB = { eB.x + c2[nt][2] + be0, eB.y + c2[nt][3] + be1 };
        *(float2*)&out_edges[gbB] = oB;
    }
}

// ---------------- K5: softmax (512 threads, 4/col) + wv = attn @ v ----------------
#define SW_L 0
#define SW_A 66048
#define SW_V 100864
#define SW_RED 111104
#define SW_SUM 113152
#define SW_SMEM 115200

__global__ void __launch_bounds__(512, 1) k_softmax_wv() {
    extern __shared__ char smem[];
    const uint32_t sb = smem_to_u32(smem);
    float* s_l = (float*)(smem + SW_L);
    float* s_red = (float*)(smem + SW_RED);
    float* s_sum = (float*)(smem + SW_SUM);
    int t = threadIdx.x, lane = t & 31, wid = t >> 5;
    int bh = blockIdx.x;
    int b = bh >> 3, h = bh & 7;
    const float* L = g_logits + bh * 128 * 128;

    for (int u = t; u < 16384; u += 512) {
        int qq = u >> 7, kk = u & 127;
        s_l[qq * 129 + kk] = L[u];
    }
    {
        int kk = t >> 2, c4 = t & 3;
        *(uint4*)(smem + SW_V + kk * 80 + c4 * 16) =
            *(const uint4*)(g_v_bf16 + (b * 128 + kk) * 256 + h * 32 + c4 * 8);
    }
    __syncthreads();

    {
        int k = t & 127, s = t >> 7;
        int q0 = s * 32;
        float m = -1e30f;
        for (int qq = q0; qq < q0 + 32; qq++) m = fmaxf(m, s_l[qq * 129 + k]);
        s_red[t] = m;
        __syncthreads();
        float gm = fmaxf(fmaxf(s_red[k], s_red[128 + k]),
                         fmaxf(s_red[256 + k], s_red[384 + k]));
        float sum = 0.f;
        for (int qq = q0; qq < q0 + 32; qq++) {
            float e = __expf(s_l[qq * 129 + k] - gm);
            s_l[qq * 129 + k] = e;
            sum += e;
        }
        s_sum[t] = sum;
        __syncthreads();
        float inv = 1.f / (s_sum[k] + s_sum[128 + k] + s_sum[256 + k] + s_sum[384 + k]);
        for (int qq = q0; qq < q0 + 32; qq++)
            *(__nv_bfloat16*)(smem + SW_A + (qq * 136 + k) * 2) =
                __float2bfloat16(s_l[qq * 129 + k] * inv);
    }
    __syncthreads();

    if (wid < 8) {
        int m0 = wid * 16;
        int gid = lane >> 2, tig = lane & 3;
        float acc[4][4];
#pragma unroll
        for (int i = 0; i < 4; i++)
#pragma unroll
            for (int e = 0; e < 4; e++) acc[i][e] = 0.f;
#pragma unroll
        for (int kk = 0; kk < 8; kk++) {
            uint32_t af[4];
            ldsm_x4(af, ldsm_addr(sb + SW_A, 136, m0, kk * 16, lane));
#pragma unroll
            for (int np = 0; np < 2; np++) {
                uint32_t bfr[4];
                ldsm_x4_t(bfr, ldsm_addr(sb + SW_V, 40, kk * 16, np * 16, lane));
                mma_bf16(acc[np * 2], af, bfr);
                mma_bf16(acc[np * 2 + 1], af, bfr + 2);
            }
        }
#pragma unroll
        for (int nt = 0; nt < 4; nt++) {
            int n = nt * 8 + tig * 2;
            int rA = m0 + gid;
            float2 oA = { acc[nt][0], acc[nt][1] };
            *(float2*)&g_wv[(b * 128 + rA) * 256 + h * 32 + n] = oA;
            float2 oB = { acc[nt][2], acc[nt][3] };
            *(float2*)&g_wv[(b * 128 + rA + 8) * 256 + h * 32 + n] = oB;
        }
    }
}

// ---------------- K6: fused node delta + residual + LN/FiLM -> n_out bf16 ----------------
__global__ void k_node_fuse(const float* __restrict__ nodes, const float* __restrict__ Wno,
                            const float* __restrict__ bno, float* __restrict__ out_nodes) {
    __shared__ float s_wv[256];
    __shared__ float s_red[16];
    int row = blockIdx.x, t = threadIdx.x;
    int b = row >> 7;
    s_wv[t] = g_wv[row * 256 + t];
    __syncthreads();
    float acc = bno[t];
#pragma unroll 4
    for (int c = 0; c < 256; c++) acc = fmaf(s_wv[c], Wno[c * 256 + t], acc);
    float x = nodes[row * 256 + t] + acc;
    out_nodes[row * 256 + t] = x;
    float ws = warpSum(x);
    float wq = warpSum(x * x);
    int lane = t & 31, w = t >> 5;
    if (lane == 0) { s_red[w] = ws; s_red[8 + w] = wq; }
    __syncthreads();
    float s = 0.f, sq = 0.f;
#pragma unroll
    for (int i = 0; i < 8; i++) { s += s_red[i]; sq += s_red[8 + i]; }
    float mean = s * (1.f / 256.f);
    float var = sq * (1.f / 256.f) - mean * mean;
    float inv = rsqrtf(var + 1e-5f);
    float y = (x - mean) * inv;
    y = y * (1.f + g_cond[b * 1024 + 512 + t]) + g_cond[b * 1024 + 768 + t];
    g_nout_bf16[row * 256 + t] = __float2bfloat16(lrelu(y));
}

// ---------------- K7b: h1 = lrelu(n_out @ Wn1 + bn1) ----------------
#define NA_OFF 0        // [32][264] bf16 = 16896
#define NB_OFF 33792    // [256][136] bf16 = 69632
#define NM_SMEM 103424

__global__ void __launch_bounds__(256, 2)
k_nmlp1(const float* __restrict__ bn1) {
    extern __shared__ char smem[];
    const uint32_t sb = smem_to_u32(smem);
    int t = threadIdx.x, lane = t & 31, wid = t >> 5;
    int mi = blockIdx.x, nj = blockIdx.y;
    int m0 = (wid & 1) * 16, n0 = (wid >> 1) * 32;
    int gid = lane >> 2, tig = lane & 3;

    for (int u = t; u < 1024; u += 256) {
        int r = u >> 5, c16 = u & 31;
        *(uint4*)(smem + NA_OFF + r * 528 + c16 * 16) =
            *(const uint4*)(g_nout_bf16 + (mi * 32 + r) * 256 + c16 * 8);
    }
    for (int u = t; u < 4096; u += 256) {
        int r = u >> 4, c16 = u & 15;
        *(uint4*)(smem + NB_OFF + r * 272 + c16 * 16) =
            *(const uint4*)(g_wn1_bf16 + r * 1024 + nj * 128 + c16 * 8);
    }
    __syncthreads();

    float c2[4][4];
#pragma unroll
    for (int i = 0; i < 4; i++)
#pragma unroll
        for (int e = 0; e < 4; e++) c2[i][e] = 0.f;
#pragma unroll
    for (int kk = 0; kk < 16; kk++) {
        uint32_t af[4];
        ldsm_x4(af, ldsm_addr(sb + NA_OFF, 264, m0, kk * 16, lane));
#pragma unroll
        for (int np = 0; np < 2; np++) {
            uint32_t bfr[4];
            ldsm_x4_t(bfr, ldsm_addr(sb + NB_OFF, 136, kk * 16, n0 + np * 16, lane));
            mma_bf16(c2[np * 2], af, bfr);
            mma_bf16(c2[np * 2 + 1], af, bfr + 2);
        }
    }
#pragma unroll
    for (int nt = 0; nt < 4; nt++) {
        int gcol = nj * 128 + n0 + nt * 8 + tig * 2;
        float b0 = __ldg(&bn1[gcol]), b1 = __ldg(&bn1[gcol + 1]);
        int rA = mi * 32 + m0 + gid, rB = rA + 8;
        *(__nv_bfloat162*)&g_h1_bf16[rA * 1024 + gcol] =
            __floats2bfloat162_rn(lrelu(c2[nt][0] + b0), lrelu(c2[nt][1] + b1));
        *(__nv_bfloat162*)&g_h1_bf16[rB * 1024 + gcol] =
            __floats2bfloat162_rn(lrelu(c2[nt][2] + b0), lrelu(c2[nt][3] + b1));
    }
}

// ---------------- K7c: nodes_out += h1 @ Wn2 + bn2 ----------------
__global__ void __launch_bounds__(256, 2)
k_nmlp2(const float* __restrict__ bn2, float* __restrict__ out_nodes) {
    extern __shared__ char smem[];
    const uint32_t sb = smem_to_u32(smem);
    int t = threadIdx.x, lane = t & 31, wid = t >> 5;
    int mi = blockIdx.x, nj = blockIdx.y;
    int m0 = (wid & 1) * 16, n0 = (wid >> 1) * 32;
    int gid = lane >> 2, tig = lane & 3;

    float c2[4][4];
#pragma unroll
    for (int i = 0; i < 4; i++)
#pragma unroll
        for (int e = 0; e < 4; e++) c2[i][e] = 0.f;

    for (int kc = 0; kc < 4; kc++) {
        for (int u = t; u < 1024; u += 256) {
            int r = u >> 5, c16 = u & 31;
            *(uint4*)(smem + NA_OFF + r * 528 + c16 * 16) =
                *(const uint4*)(g_h1_bf16 + (mi * 32 + r) * 1024 + kc * 256 + c16 * 8);
        }
        for (int u = t; u < 4096; u += 256) {
            int r = u >> 4, c16 = u & 15;
            *(uint4*)(smem + NB_OFF + r * 272 + c16 * 16) =
                *(const uint4*)(g_wn2_bf16 + (kc * 256 + r) * 256 + nj * 128 + c16 * 8);
        }
        __syncthreads();
#pragma unroll
        for (int kk = 0; kk < 16; kk++) {
            uint32_t af[4];
            ldsm_x4(af, ldsm_addr(sb + NA_OFF, 264, m0, kk * 16, lane));
#pragma unroll
            for (int np = 0; np < 2; np++) {
                uint32_t bfr[4];
                ldsm_x4_t(bfr, ldsm_addr(sb + NB_OFF, 136, kk * 16, n0 + np * 16, lane));
                mma_bf16(c2[np * 2], af, bfr);
                mma_bf16(c2[np * 2 + 1], af, bfr + 2);
            }
        }
        __syncthreads();
    }
#pragma unroll
    for (int nt = 0; nt < 4; nt++) {
        int gcol = nj * 128 + n0 + nt * 8 + tig * 2;
        float b0 = __ldg(&bn2[gcol]), b1 = __ldg(&bn2[gcol + 1]);
        int rA = mi * 32 + m0 + gid, rB = rA + 8;
        float2 xA = *(const float2*)&out_nodes[rA * 256 + gcol];
        float2 oA = { xA.x + c2[nt][0] + b0, xA.y + c2[nt][1] + b1 };
        *(float2*)&out_nodes[rA * 256 + gcol] = oA;
        float2 xB = *(const float2*)&out_nodes[rB * 256 + gcol];
        float2 oB = { xB.x + c2[nt][2] + b0, xB.y + c2[nt][3] + b1 };
        *(float2*)&out_nodes[rB * 256 + gcol] = oB;
    }
}

// ---------------- K8: edge LN-MLP (512 threads / 16 warps) ----------------
#define EM_W1 0
#define EM_W2 34816
#define EM_A  69632
#define EM_BE 104448
#define EM_SMEM 105472

__global__ void __launch_bounds__(512, 1)
k_edge_mlp(const float* __restrict__ be1, const float* __restrict__ be2,
           float* __restrict__ edges_io) {
    extern __shared__ char smem[];
    const uint32_t sb = smem_to_u32(smem);
    float* s_be1 = (float*)(smem + EM_BE);
    float* s_be2 = (float*)(smem + EM_BE + 512);
    int t = threadIdx.x, lane = t & 31, wid = t >> 5;
    int rows0 = blockIdx.x * 128;
    int strip = wid & 7, half = wid >> 3;
    int m0 = strip * 16, n0 = half * 64;
    int gid = lane >> 2, tig = lane & 3;

    for (int u = t; u < 2048; u += 512) {
        int r = u >> 4, c16 = u & 15;
        *(uint4*)(smem + EM_W1 + r * 272 + c16 * 16) = *(const uint4*)(g_we1_bf16 + r * 128 + c16 * 8);
        *(uint4*)(smem + EM_W2 + r * 272 + c16 * 16) = *(const uint4*)(g_we2_bf16 + r * 128 + c16 * 8);
    }
    if (t < 128) { s_be1[t] = be1[t]; s_be2[t] = be2[t]; }

    for (int rr = 0; rr < 8; rr++) {
        int r = wid * 8 + rr;
        int gbase = (rows0 + r) * 128;
        float v0 = edges_io[gbase + lane], v1 = edges_io[gbase + lane + 32],
              v2 = edges_io[gbase + lane + 64], v3 = edges_io[gbase + lane + 96];
        float s = warpSum(v0 + v1 + v2 + v3);
        float sq = warpSum(v0 * v0 + v1 * v1 + v2 * v2 + v3 * v3);
        float mean = s * (1.f / 128.f);
        float inv = rsqrtf(sq * (1.f / 128.f) - mean * mean + 1e-5f);
        float vv[4] = {v0, v1, v2, v3};
#pragma unroll
        for (int cc = 0; cc < 4; cc++) {
            int c = lane + cc * 32;
            *(__nv_bfloat16*)(smem + EM_A + r * 272 + c * 2) =
                __float2bfloat16(lrelu((vv[cc] - mean) * inv));
        }
    }
    __syncthreads();

    float c1[8][4];
#pragma unroll
    for (int i = 0; i < 8; i++)
#pragma unroll
        for (int e = 0; e < 4; e++) c1[i][e] = 0.f;
#pragma unroll
    for (int kk = 0; kk < 8; kk++) {
        uint32_t af[4];
        ldsm_x4(af, ldsm_addr(sb + EM_A, 136, m0, kk * 16, lane));
#pragma unroll
        for (int np = 0; np < 4; np++) {
            uint32_t bfr[4];
            ldsm_x4_t(bfr, ldsm_addr(sb + EM_W1, 136, kk * 16, n0 + np * 16, lane));
            mma_bf16(c1[np * 2], af, bfr);
            mma_bf16(c1[np * 2 + 1], af, bfr + 2);
        }
    }
    __syncthreads();
#pragma unroll
    for (int nt = 0; nt < 8; nt++) {
        int n = n0 + nt * 8 + tig * 2;
        float b0 = s_be1[n], b1 = s_be1[n + 1];
        int rA = m0 + gid;
        *(__nv_bfloat162*)(smem + EM_A + rA * 272 + n * 2) =
            __floats2bfloat162_rn(lrelu(c1[nt][0] + b0), lrelu(c1[nt][1] + b1));
        *(__nv_bfloat162*)(smem + EM_A + (rA + 8) * 272 + n * 2) =
            __floats2bfloat162_rn(lrelu(c1[nt][2] + b0), lrelu(c1[nt][3] + b1));
    }
    __syncthreads();

    float c2[8][4];
#pragma unroll
    for (int i = 0; i < 8; i++)
#pragma unroll
        for (int e = 0; e < 4; e++) c2[i][e] = 0.f;
#pragma unroll
    for (int kk = 0; kk < 8; kk++) {
        uint32_t af[4];
        ldsm_x4(af, ldsm_addr(sb + EM_A, 136, m0, kk * 16, lane));
#pragma unroll
        for (int np = 0; np < 4; np++) {
            uint32_t bfr[4];
            ldsm_x4_t(bfr, ldsm_addr(sb + EM_W2, 136, kk * 16, n0 + np * 16, lane));
            mma_bf16(c2[np * 2], af, bfr);
            mma_bf16(c2[np * 2 + 1], af, bfr + 2);
        }
    }
#pragma unroll
    for (int nt = 0; nt < 8; nt++) {
        int n = n0 + nt * 8 + tig * 2;
        float b0 = s_be2[n], b1 = s_be2[n + 1];
        int rA = m0 + gid;
        int gbA = (rows0 + rA) * 128 + n;
        float2 eA = *(const float2*)&edges_io[gbA];
        float2 oA = { eA.x + c2[nt][0] + b0, eA.y + c2[nt][1] + b1 };
        *(float2*)&edges_io[gbA] = oA;
        int gbB = gbA + 8 * 128;
        float2 eB = *(const float2*)&edges_io[gbB];
        float2 oB = { eB.x + c2[nt][2] + b0, eB.y + c2[nt][3] + b1 };
        *(float2*)&edges_io[gbB] = oB;
    }
}

// ---------------- stream/event infrastructure ----------------
struct ForkCtx {
    cudaStream_t s1 = nullptr;
    cudaEvent_t e_begin = nullptr, e_prep = nullptr, e_main = nullptr, e_edge = nullptr;
    bool ok = false;
    ForkCtx() {
        ok = (cudaStreamCreateWithFlags(&s1, cudaStreamNonBlocking) == cudaSuccess) &&
             (cudaEventCreateWithFlags(&e_begin, cudaEventDisableTiming) == cudaSuccess) &&
             (cudaEventCreateWithFlags(&e_prep, cudaEventDisableTiming) == cudaSuccess) &&
             (cudaEventCreateWithFlags(&e_main, cudaEventDisableTiming) == cudaSuccess) &&
             (cudaEventCreateWithFlags(&e_edge, cudaEventDisableTiming) == cudaSuccess);
    }
};
static ForkCtx g_fork;

// ---------------- launch ----------------
extern "C" void kernel_launch(void* const* d_in, const int* in_sizes, int n_in,
                              void* d_out, int out_size) {
    const float* nodes = (const float*)d_in[0];
    const float* edges = (const float*)d_in[1];
    const float* conds = (const float*)d_in[2];
    const float* Wc   = (const float*)d_in[3];
    const float* bc   = (const float*)d_in[4];
    const float* Wqkv = (const float*)d_in[5];
    const float* bqkv = (const float*)d_in[6];
    const float* Wss  = (const float*)d_in[7];
    const float* bss  = (const float*)d_in[8];
    const float* Wno  = (const float*)d_in[9];
    const float* bno  = (const float*)d_in[10];
    const float* Weo  = (const float*)d_in[11];
    const float* beo  = (const float*)d_in[12];
    const float* Wn1  = (const float*)d_in[13];
    const float* bn1  = (const float*)d_in[14];
    const float* Wn2  = (const float*)d_in[15];
    const float* bn2  = (const float*)d_in[16];
    const float* We1  = (const float*)d_in[17];
    const float* be1  = (const float*)d_in[18];
    const float* We2  = (const float*)d_in[19];
    const float* be2  = (const float*)d_in[20];

    float* out_nodes = (float*)d_out;
    float* out_edges = out_nodes + NB * NN * ND;

    cudaFuncSetAttribute(k_qkv, cudaFuncAttributeMaxDynamicSharedMemorySize, QKV_SMEM);
    cudaFuncSetAttribute(k_edge_main, cudaFuncAttributeMaxDynamicSharedMemorySize, E_SMEM);
    cudaFuncSetAttribute(k_softmax_wv, cudaFuncAttributeMaxDynamicSharedMemorySize, SW_SMEM);
    cudaFuncSetAttribute(k_nmlp1, cudaFuncAttributeMaxDynamicSharedMemorySize, NM_SMEM);
    cudaFuncSetAttribute(k_nmlp2, cudaFuncAttributeMaxDynamicSharedMemorySize, NM_SMEM);
    cudaFuncSetAttribute(k_edge_mlp, cudaFuncAttributeMaxDynamicSharedMemorySize, EM_SMEM);

    if (g_fork.ok) {
        // fork 1: prep on s1 || cond->nin on default
        cudaEventRecord(g_fork.e_begin, 0);
        cudaStreamWaitEvent(g_fork.s1, g_fork.e_begin, 0);
        k_prep<<<1024, 256, 0, g_fork.s1>>>(Wss, Weo, Wqkv, We1, We2, Wn1, Wn2);
        cudaEventRecord(g_fork.e_prep, g_fork.s1);
        k_cond<<<4, 1024>>>(conds, Wc, bc);
        k_nin<<<512, 256>>>(nodes);
        cudaStreamWaitEvent(0, g_fork.e_prep, 0);
        k_qkv<<<dim3(32, 6), 256, QKV_SMEM>>>(bqkv);
        k_edge_main<<<dim3(128, 4), 512, E_SMEM>>>(edges, bss, beo, out_edges);
        // fork 2: edge_mlp on s1 || node branch on default
        cudaEventRecord(g_fork.e_main, 0);
        cudaStreamWaitEvent(g_fork.s1, g_fork.e_main, 0);
        k_edge_mlp<<<512, 512, EM_SMEM, g_fork.s1>>>(be1, be2, out_edges);
        cudaEventRecord(g_fork.e_edge, g_fork.s1);
        k_softmax_wv<<<32, 512, SW_SMEM>>>();
        k_node_fuse<<<512, 256>>>(nodes, Wno, bno, out_nodes);
        k_nmlp1<<<dim3(16, 8), 256, NM_SMEM>>>(bn1);
        k_nmlp2<<<dim3(16, 2), 256, NM_SMEM>>>(bn2, out_nodes);
        cudaStreamWaitEvent(0, g_fork.e_edge, 0);
    } else {
        k_prep<<<1024, 256>>>(Wss, Weo, Wqkv, We1, We2, Wn1, Wn2);
        k_cond<<<4, 1024>>>(conds, Wc, bc);
        k_nin<<<512, 256>>>(nodes);
        k_qkv<<<dim3(32, 6), 256, QKV_SMEM>>>(bqkv);
        k_edge_main<<<dim3(128, 4), 512, E_SMEM>>>(edges, bss, beo, out_edges);
        k_softmax_wv<<<32, 512, SW_SMEM>>>();
        k_node_fuse<<<512, 256>>>(nodes, Wno, bno, out_nodes);
        k_nmlp1<<<dim3(16, 8), 256, NM_SMEM>>>(bn1);
        k_nmlp2<<<dim3(16, 2), 256, NM_SMEM>>>(bn2, out_nodes);
        k_edge_mlp<<<512, 512, EM_SMEM>>>(be1, be2, out_edges);
    }
}